// round 1
// baseline (speedup 1.0000x reference)
#include <cuda_runtime.h>

#define SQ 2048
#define DM 512
#define NB 2
#define MS (NB*SQ)   // 4096

// ---------------- scratch (static device globals; no allocation) ----------------
__device__ float g_Q[MS*DM];
__device__ float g_K[MS*DM];
__device__ float g_V[MS*DM];
__device__ float g_scores[NB*SQ*SQ];
__device__ float g_attn1[NB*SQ*SQ];
__device__ float g_attn2[NB*SQ*(SQ/2)];
__device__ float g_attn4[NB*SQ*(SQ/4)];
__device__ float g_attn8[NB*SQ*(SQ/8)];
__device__ float g_ctx[MS*DM];
__device__ float g_comb[MS*4*DM];

// ---------------- generic NN GEMM: C = alpha*(A @ B) + bias ----------------
// B logical row k lives at physical offset k*ldbStep (supports dilated V rows).
// cdiv > 0: causal truncation of the k loop: kmax = (i_max_of_block)/cdiv + 1.
// All dims are multiples of the tile sizes (64/64/16) by construction -> no bounds checks.
__global__ __launch_bounds__(256) void gemm_nn(
    const float* __restrict__ A, const float* __restrict__ Bm,
    const float* __restrict__ bias, float* __restrict__ C,
    int M, int N, int K, int lda, int ldbStep, int ldc,
    long strideA, long strideB, long strideC,
    int cdiv, float alpha)
{
    int bz = blockIdx.z;
    A  += (long)bz * strideA;
    Bm += (long)bz * strideB;
    C  += (long)bz * strideC;

    int i0 = blockIdx.y * 64;
    int n0 = blockIdx.x * 64;
    int tid = threadIdx.x;
    int tx = tid & 15, ty = tid >> 4;

    __shared__ float As[16][68];
    __shared__ float Bs[16][64];

    float acc[4][4] = {};

    int ktiles;
    if (cdiv > 0) {
        int kmax = (i0 + 63) / cdiv + 1;
        if (kmax > K) kmax = K;
        ktiles = (kmax + 15) >> 4;
    } else {
        ktiles = K >> 4;
    }

    int ar = tid >> 2;          // 0..63  (A row within tile)
    int ac = (tid & 3) * 4;     // 0,4,8,12 (A col group)
    int br = tid >> 4;          // 0..15  (B k-row within tile)
    int bc = (tid & 15) * 4;    // B col group

    for (int kt = 0; kt < ktiles; kt++) {
        int k0 = kt * 16;
        float4 av = *(const float4*)&A[(long)(i0 + ar) * lda + k0 + ac];
        As[ac+0][ar] = av.x; As[ac+1][ar] = av.y;
        As[ac+2][ar] = av.z; As[ac+3][ar] = av.w;
        float4 bv = *(const float4*)&Bm[(long)(k0 + br) * ldbStep + n0 + bc];
        *(float4*)&Bs[br][bc] = bv;
        __syncthreads();
        #pragma unroll
        for (int kk = 0; kk < 16; kk++) {
            float4 a4 = *(const float4*)&As[kk][ty*4];
            float4 b4 = *(const float4*)&Bs[kk][tx*4];
            float a[4] = {a4.x, a4.y, a4.z, a4.w};
            float b[4] = {b4.x, b4.y, b4.z, b4.w};
            #pragma unroll
            for (int i = 0; i < 4; i++)
                #pragma unroll
                for (int j = 0; j < 4; j++)
                    acc[i][j] += a[i] * b[j];
        }
        __syncthreads();
    }

    float bvals[4] = {0.f, 0.f, 0.f, 0.f};
    if (bias) {
        #pragma unroll
        for (int j = 0; j < 4; j++) bvals[j] = bias[n0 + tx*4 + j];
    }
    #pragma unroll
    for (int i = 0; i < 4; i++) {
        int row = i0 + ty*4 + i;
        float4 o;
        o.x = acc[i][0]*alpha + bvals[0];
        o.y = acc[i][1]*alpha + bvals[1];
        o.z = acc[i][2]*alpha + bvals[2];
        o.w = acc[i][3]*alpha + bvals[3];
        *(float4*)&C[(long)row*ldc + n0 + tx*4] = o;
    }
}

// ---------------- NT GEMM for scores: C[i,j] = alpha * sum_d A[i,d]*Bt[j,d] ----------------
// Skips fully-masked (j tile entirely above diagonal) blocks; those outputs are never read.
__global__ __launch_bounds__(256) void gemm_nt_scores(
    const float* __restrict__ A, const float* __restrict__ Bt,
    float* __restrict__ C,
    int K, int lda, int ldb, int ldc,
    long strideA, long strideB, long strideC, float alpha)
{
    int i0 = blockIdx.y * 64;
    int j0 = blockIdx.x * 64;
    if (j0 > i0 + 63) return;   // whole tile masked for every rate

    int bz = blockIdx.z;
    A  += (long)bz * strideA;
    Bt += (long)bz * strideB;
    C  += (long)bz * strideC;

    int tid = threadIdx.x;
    int tx = tid & 15, ty = tid >> 4;

    __shared__ float As[16][68];
    __shared__ float Bs[16][68];

    float acc[4][4] = {};

    int ar = tid >> 2;
    int ac = (tid & 3) * 4;

    int ktiles = K >> 4;
    for (int kt = 0; kt < ktiles; kt++) {
        int k0 = kt * 16;
        float4 av = *(const float4*)&A[(long)(i0 + ar) * lda + k0 + ac];
        As[ac+0][ar] = av.x; As[ac+1][ar] = av.y;
        As[ac+2][ar] = av.z; As[ac+3][ar] = av.w;
        float4 bv = *(const float4*)&Bt[(long)(j0 + ar) * ldb + k0 + ac];
        Bs[ac+0][ar] = bv.x; Bs[ac+1][ar] = bv.y;
        Bs[ac+2][ar] = bv.z; Bs[ac+3][ar] = bv.w;
        __syncthreads();
        #pragma unroll
        for (int kk = 0; kk < 16; kk++) {
            float4 a4 = *(const float4*)&As[kk][ty*4];
            float4 b4 = *(const float4*)&Bs[kk][tx*4];
            float a[4] = {a4.x, a4.y, a4.z, a4.w};
            float b[4] = {b4.x, b4.y, b4.z, b4.w};
            #pragma unroll
            for (int i = 0; i < 4; i++)
                #pragma unroll
                for (int j = 0; j < 4; j++)
                    acc[i][j] += a[i] * b[j];
        }
        __syncthreads();
    }

    #pragma unroll
    for (int i = 0; i < 4; i++) {
        int row = i0 + ty*4 + i;
        float4 o;
        o.x = acc[i][0]*alpha; o.y = acc[i][1]*alpha;
        o.z = acc[i][2]*alpha; o.w = acc[i][3]*alpha;
        *(float4*)&C[(long)row*ldc + j0 + tx*4] = o;
    }
}

// ---------------- block reductions ----------------
__device__ __forceinline__ float blockReduceMax(float v, float* red) {
    int tid = threadIdx.x;
    red[tid] = v;
    __syncthreads();
    #pragma unroll
    for (int s = 128; s >= 1; s >>= 1) {
        if (tid < s) red[tid] = fmaxf(red[tid], red[tid + s]);
        __syncthreads();
    }
    float r = red[0];
    __syncthreads();
    return r;
}
__device__ __forceinline__ float blockReduceSum(float v, float* red) {
    int tid = threadIdx.x;
    red[tid] = v;
    __syncthreads();
    #pragma unroll
    for (int s = 128; s >= 1; s >>= 1) {
        if (tid < s) red[tid] = red[tid] + red[tid + s];
        __syncthreads();
    }
    float r = red[0];
    __syncthreads();
    return r;
}

// ---------------- masked softmax for all 4 rates + avg attention ----------------
// One block per (b, i) row. Writes compacted attn per rate and the avg map to d_out.
__global__ __launch_bounds__(256) void softmax_kernel(float* __restrict__ avg_out)
{
    __shared__ float srow[SQ];
    __shared__ float avgs[SQ];
    __shared__ float red[256];

    int i = blockIdx.x;
    int b = blockIdx.y;
    int tid = threadIdx.x;

    const float* sc = &g_scores[((long)b*SQ + i) * SQ];
    for (int j = tid; j <= i; j += 256) srow[j] = sc[j];
    for (int j = tid; j < SQ; j += 256) avgs[j] = 0.f;
    __syncthreads();

    #pragma unroll
    for (int rr = 0; rr < 4; rr++) {
        const int rate = 1 << rr;
        const int Sr = SQ >> rr;
        float* attn;
        if (rr == 0)      attn = g_attn1;
        else if (rr == 1) attn = g_attn2;
        else if (rr == 2) attn = g_attn4;
        else              attn = g_attn8;

        int count = i / rate + 1;

        float mx = -1e30f;
        for (int m = tid; m < count; m += 256) mx = fmaxf(mx, srow[m*rate]);
        mx = blockReduceMax(mx, red);

        float sum = 0.f;
        for (int m = tid; m < count; m += 256) sum += __expf(srow[m*rate] - mx);
        sum = blockReduceSum(sum, red);
        float inv = 1.0f / sum;

        float* arow = attn + ((long)b*SQ + i) * Sr;
        for (int m = tid; m < Sr; m += 256) {
            float v = 0.f;
            if (m < count) {
                v = __expf(srow[m*rate] - mx) * inv;
                avgs[m*rate] += 0.25f * v;   // each (rate, j) touched by exactly one thread
            }
            arow[m] = v;
        }
        __syncthreads();
    }

    float* out = avg_out + ((long)b*SQ + i) * SQ;
    for (int j = tid; j < SQ; j += 256) out[j] = (j <= i) ? avgs[j] : 0.f;
}

// ---------------- launch ----------------
extern "C" void kernel_launch(void* const* d_in, const int* in_sizes, int n_in,
                              void* d_out, int out_size) {
    const float* x  = (const float*)d_in[0];
    const float* Wq = (const float*)d_in[1];
    const float* bq = (const float*)d_in[2];
    const float* Wk = (const float*)d_in[3];
    const float* bk = (const float*)d_in[4];
    const float* Wv = (const float*)d_in[5];
    const float* bv = (const float*)d_in[6];
    const float* Wr = (const float*)d_in[7];
    const float* br = (const float*)d_in[8];
    const float* Wo = (const float*)d_in[9];
    const float* bo = (const float*)d_in[10];
    float* out = (float*)d_out;

    float *Qp, *Kp, *Vp, *scp, *a1, *a2, *a4, *a8, *ctxp, *combp;
    cudaGetSymbolAddress((void**)&Qp, g_Q);
    cudaGetSymbolAddress((void**)&Kp, g_K);
    cudaGetSymbolAddress((void**)&Vp, g_V);
    cudaGetSymbolAddress((void**)&scp, g_scores);
    cudaGetSymbolAddress((void**)&a1, g_attn1);
    cudaGetSymbolAddress((void**)&a2, g_attn2);
    cudaGetSymbolAddress((void**)&a4, g_attn4);
    cudaGetSymbolAddress((void**)&a8, g_attn8);
    cudaGetSymbolAddress((void**)&ctxp, g_ctx);
    cudaGetSymbolAddress((void**)&combp, g_comb);

    dim3 blk(256);

    // QKV projections: [4096,512] = x @ W + b
    {
        dim3 grid(DM/64, MS/64, 1);
        gemm_nn<<<grid, blk>>>(x, Wq, bq, Qp, MS, DM, DM, DM, DM, DM, 0, 0, 0, 0, 1.f);
        gemm_nn<<<grid, blk>>>(x, Wk, bk, Kp, MS, DM, DM, DM, DM, DM, 0, 0, 0, 0, 1.f);
        gemm_nn<<<grid, blk>>>(x, Wv, bv, Vp, MS, DM, DM, DM, DM, DM, 0, 0, 0, 0, 1.f);
    }

    // scores = Q @ K^T / sqrt(D), batched, lower-triangle tiles only
    {
        dim3 grid(SQ/64, SQ/64, NB);
        const float alpha = 0.044194173824159216f; // 1/sqrt(512)
        gemm_nt_scores<<<grid, blk>>>(Qp, Kp, scp, DM, DM, DM, SQ,
                                      (long)SQ*DM, (long)SQ*DM, (long)SQ*SQ, alpha);
    }

    // masked softmax for all rates + avg attention into second half of d_out
    {
        dim3 grid(SQ, NB);
        softmax_kernel<<<grid, blk>>>(out + (long)MS*DM);
    }

    // per-rate: ctx = attn_c @ V(dilated rows), then proj into combined columns
    float* attnPtrs[4] = {a1, a2, a4, a8};
    for (int rr = 0; rr < 4; rr++) {
        int rate = 1 << rr;
        int Sr = SQ >> rr;
        {
            dim3 grid(DM/64, SQ/64, NB);
            gemm_nn<<<grid, blk>>>(attnPtrs[rr], Vp, nullptr, ctxp,
                                   SQ, DM, Sr, Sr, rate*DM, DM,
                                   (long)SQ*Sr, (long)SQ*DM, (long)SQ*DM,
                                   rate, 1.f);
        }
        {
            dim3 grid(DM/64, MS/64, 1);
            gemm_nn<<<grid, blk>>>(ctxp, Wr + (long)rr*DM*DM, br + (long)rr*DM,
                                   combp + (long)rr*DM,
                                   MS, DM, DM, DM, DM, 4*DM,
                                   0, 0, 0, 0, 1.f);
        }
    }

    // output = combined @ Wo + bo  -> first part of d_out
    {
        dim3 grid(DM/64, MS/64, 1);
        gemm_nn<<<grid, blk>>>(combp, Wo, bo, out, MS, DM, 4*DM, 4*DM, DM, DM,
                               0, 0, 0, 0, 1.f);
    }
}

// round 2
// speedup vs baseline: 1.9560x; 1.9560x over previous
#include <cuda_runtime.h>
#include <cstdint>

#define SQ 2048
#define DM 512
#define NB 2
#define MS (NB*SQ)   // 4096

#define BM 128
#define BN 128
#define BK 16
#define APITCH 20    // As row pitch (floats): conflict-free A-frag loads
#define BPITCH 136   // Bs row pitch (floats): conflict-free B-frag loads

// ---------------- scratch (static device globals; no allocation) ----------------
__device__ float g_Q[MS*DM];
__device__ float g_K[MS*DM];
__device__ float g_V[MS*DM];
__device__ float g_scores[(long)NB*SQ*SQ];
__device__ float g_attn1[(long)NB*SQ*SQ];
__device__ float g_attn2[(long)NB*SQ*(SQ/2)];
__device__ float g_attn4[(long)NB*SQ*(SQ/4)];
__device__ float g_attn8[(long)NB*SQ*(SQ/8)];
__device__ float g_ctx4[4L*MS*DM];
__device__ float g_comb[(long)MS*4*DM];

__device__ __forceinline__ uint32_t f2tf(float f) {
    uint32_t u;
    asm("cvt.rna.tf32.f32 %0, %1;" : "=r"(u) : "f"(f));
    return u;
}

__device__ __forceinline__ void mma8(float* c, const uint32_t* a, const uint32_t* b) {
    asm volatile(
        "mma.sync.aligned.m16n8k8.row.col.f32.tf32.tf32.f32 "
        "{%0,%1,%2,%3}, {%4,%5,%6,%7}, {%8,%9}, {%0,%1,%2,%3};"
        : "+f"(c[0]), "+f"(c[1]), "+f"(c[2]), "+f"(c[3])
        : "r"(a[0]), "r"(a[1]), "r"(a[2]), "r"(a[3]), "r"(b[0]), "r"(b[1]));
}

// ---------------- 128x128x(16*ktiles) tf32 MMA tile core ----------------
// NT=false: B row-major [K,N] with physical row step ldb (supports dilated V rows).
// NT=true : B is [N,K] row-major (scores: K-matrix), loaded transposed into Bs.
template<bool NT>
__device__ __forceinline__ void gemm_mma_tile(
    const float* __restrict__ A, const float* __restrict__ B,
    const float* __restrict__ bias, float* __restrict__ C,
    int i0, int n0, int ktiles, int lda, int ldb, int ldc, float alpha)
{
    __shared__ uint32_t As[2][BM*APITCH];
    __shared__ uint32_t Bs[2][BK*BPITCH];

    const int tid  = threadIdx.x;
    const int lane = tid & 31;
    const int wid  = tid >> 5;
    const int wm   = wid >> 2;        // 0..1
    const int wn   = wid & 3;         // 0..3
    const int gq   = lane >> 2;       // group id 0..7
    const int tg   = lane & 3;        // thread-in-group 0..3

    float acc[4][4][4];
    #pragma unroll
    for (int a = 0; a < 4; a++)
        #pragma unroll
        for (int b2 = 0; b2 < 4; b2++)
            #pragma unroll
            for (int c = 0; c < 4; c++) acc[a][b2][c] = 0.f;

    float4 sa[2], sb[2];

    // ---- prologue: load tile 0 ----
    #pragma unroll
    for (int j = 0; j < 2; j++) {
        int e = tid + j*256;
        int m = e >> 2, kq = e & 3;
        sa[j] = *(const float4*)&A[(long)(i0+m)*lda + kq*4];
        if (NT) {
            int n = e >> 2, kq2 = e & 3;
            sb[j] = *(const float4*)&B[(long)(n0+n)*ldb + kq2*4];
        } else {
            int kr = e >> 5, nq = e & 31;
            sb[j] = *(const float4*)&B[(long)kr*ldb + n0 + nq*4];
        }
    }
    #pragma unroll
    for (int j = 0; j < 2; j++) {
        int e = tid + j*256;
        {
            int m = e >> 2, kq = e & 3;
            uint4 v = make_uint4(f2tf(sa[j].x), f2tf(sa[j].y), f2tf(sa[j].z), f2tf(sa[j].w));
            *(uint4*)&As[0][m*APITCH + kq*4] = v;
        }
        if (NT) {
            int n = e >> 2, kq = e & 3;
            Bs[0][(kq*4+0)*BPITCH + n] = f2tf(sb[j].x);
            Bs[0][(kq*4+1)*BPITCH + n] = f2tf(sb[j].y);
            Bs[0][(kq*4+2)*BPITCH + n] = f2tf(sb[j].z);
            Bs[0][(kq*4+3)*BPITCH + n] = f2tf(sb[j].w);
        } else {
            int kr = e >> 5, nq = e & 31;
            uint4 v = make_uint4(f2tf(sb[j].x), f2tf(sb[j].y), f2tf(sb[j].z), f2tf(sb[j].w));
            *(uint4*)&Bs[0][kr*BPITCH + nq*4] = v;
        }
    }
    __syncthreads();

    for (int kt = 0; kt < ktiles; kt++) {
        const int cur = kt & 1;
        const bool more = (kt + 1 < ktiles);

        // ---- prefetch next tile into registers ----
        if (more) {
            int k0 = (kt+1) * BK;
            #pragma unroll
            for (int j = 0; j < 2; j++) {
                int e = tid + j*256;
                int m = e >> 2, kq = e & 3;
                sa[j] = *(const float4*)&A[(long)(i0+m)*lda + k0 + kq*4];
                if (NT) {
                    int n = e >> 2, kq2 = e & 3;
                    sb[j] = *(const float4*)&B[(long)(n0+n)*ldb + k0 + kq2*4];
                } else {
                    int kr = e >> 5, nq = e & 31;
                    sb[j] = *(const float4*)&B[(long)(k0+kr)*ldb + n0 + nq*4];
                }
            }
        }

        // ---- compute on current buffer: 2 k-steps of 8 ----
        #pragma unroll
        for (int ks = 0; ks < 2; ks++) {
            uint32_t af[4][4], bf[4][2];
            #pragma unroll
            for (int mt = 0; mt < 4; mt++) {
                int mr = wm*64 + mt*16;
                af[mt][0] = As[cur][(mr+gq  )*APITCH + ks*8 + tg    ];
                af[mt][1] = As[cur][(mr+gq+8)*APITCH + ks*8 + tg    ];
                af[mt][2] = As[cur][(mr+gq  )*APITCH + ks*8 + tg + 4];
                af[mt][3] = As[cur][(mr+gq+8)*APITCH + ks*8 + tg + 4];
            }
            #pragma unroll
            for (int nt = 0; nt < 4; nt++) {
                int nc = wn*32 + nt*8;
                bf[nt][0] = Bs[cur][(ks*8+tg  )*BPITCH + nc + gq];
                bf[nt][1] = Bs[cur][(ks*8+tg+4)*BPITCH + nc + gq];
            }
            #pragma unroll
            for (int mt = 0; mt < 4; mt++)
                #pragma unroll
                for (int nt = 0; nt < 4; nt++)
                    mma8(acc[mt][nt], af[mt], bf[nt]);
        }

        // ---- store prefetched tile into other buffer ----
        if (more) {
            int nxt = cur ^ 1;
            #pragma unroll
            for (int j = 0; j < 2; j++) {
                int e = tid + j*256;
                {
                    int m = e >> 2, kq = e & 3;
                    uint4 v = make_uint4(f2tf(sa[j].x), f2tf(sa[j].y), f2tf(sa[j].z), f2tf(sa[j].w));
                    *(uint4*)&As[nxt][m*APITCH + kq*4] = v;
                }
                if (NT) {
                    int n = e >> 2, kq = e & 3;
                    Bs[nxt][(kq*4+0)*BPITCH + n] = f2tf(sb[j].x);
                    Bs[nxt][(kq*4+1)*BPITCH + n] = f2tf(sb[j].y);
                    Bs[nxt][(kq*4+2)*BPITCH + n] = f2tf(sb[j].z);
                    Bs[nxt][(kq*4+3)*BPITCH + n] = f2tf(sb[j].w);
                } else {
                    int kr = e >> 5, nq = e & 31;
                    uint4 v = make_uint4(f2tf(sb[j].x), f2tf(sb[j].y), f2tf(sb[j].z), f2tf(sb[j].w));
                    *(uint4*)&Bs[nxt][kr*BPITCH + nq*4] = v;
                }
            }
        }
        __syncthreads();
    }

    // ---- epilogue ----
    #pragma unroll
    for (int nt = 0; nt < 4; nt++) {
        int col = n0 + wn*32 + nt*8 + tg*2;
        float bx = 0.f, by = 0.f;
        if (bias) { bx = bias[col]; by = bias[col+1]; }
        #pragma unroll
        for (int mt = 0; mt < 4; mt++) {
            int row = i0 + wm*64 + mt*16 + gq;
            const float* c = acc[mt][nt];
            *(float2*)&C[(long)row*ldc + col]     = make_float2(c[0]*alpha + bx, c[1]*alpha + by);
            *(float2*)&C[(long)(row+8)*ldc + col] = make_float2(c[2]*alpha + bx, c[3]*alpha + by);
        }
    }
}

// ---------------- kernels ----------------
__global__ __launch_bounds__(256,2) void k_qkv(
    const float* __restrict__ x,
    const float* __restrict__ Wq, const float* __restrict__ bq,
    const float* __restrict__ Wk, const float* __restrict__ bk,
    const float* __restrict__ Wv, const float* __restrict__ bv)
{
    int z = blockIdx.z;
    const float* W = (z == 0) ? Wq : (z == 1) ? Wk : Wv;
    const float* b = (z == 0) ? bq : (z == 1) ? bk : bv;
    float* O = (z == 0) ? g_Q : (z == 1) ? g_K : g_V;
    gemm_mma_tile<false>(x, W, b, O, blockIdx.y*BM, blockIdx.x*BN,
                         DM/BK, DM, DM, DM, 1.f);
}

__global__ __launch_bounds__(256,2) void k_scores()
{
    int i0 = blockIdx.y * BM;
    int j0 = blockIdx.x * BN;
    if (j0 > i0 + (BM-1)) return;   // fully-masked tile, never read
    int b = blockIdx.z;
    const float* Q = g_Q + (long)b*SQ*DM;
    const float* K = g_K + (long)b*SQ*DM;
    float* Cc = g_scores + (long)b*SQ*SQ;
    gemm_mma_tile<true>(Q, K, nullptr, Cc, i0, j0,
                        DM/BK, DM, DM, SQ, 0.044194173824159216f);
}

__global__ __launch_bounds__(256,2) void k_attnv()
{
    int z = blockIdx.z;
    int r = z & 3, b = z >> 2;
    int rate = 1 << r, Sr = SQ >> r;
    const float* attn = ((r==0) ? g_attn1 : (r==1) ? g_attn2 : (r==2) ? g_attn4 : g_attn8)
                        + (long)b*SQ*Sr;
    const float* V = g_V + (long)b*SQ*DM;
    float* Cc = g_ctx4 + ((long)r*NB + b)*SQ*DM;
    int i0 = blockIdx.y * BM;
    int kmax = (i0 + BM - 1)/rate + 1;     // causal truncation (compacted K dim)
    if (kmax > Sr) kmax = Sr;
    int ktiles = (kmax + BK - 1) / BK;
    gemm_mma_tile<false>(attn, V, nullptr, Cc, i0, blockIdx.x*BN,
                         ktiles, Sr, rate*DM, DM, 1.f);
}

__global__ __launch_bounds__(256,2) void k_rproj(
    const float* __restrict__ Wr, const float* __restrict__ br)
{
    int r = blockIdx.z;
    const float* A = g_ctx4 + (long)r*MS*DM;
    gemm_mma_tile<false>(A, Wr + (long)r*DM*DM, br + (long)r*DM,
                         g_comb + (long)r*DM,
                         blockIdx.y*BM, blockIdx.x*BN, DM/BK, DM, DM, 4*DM, 1.f);
}

__global__ __launch_bounds__(256,2) void k_final(
    const float* __restrict__ Wo, const float* __restrict__ bo, float* __restrict__ out)
{
    gemm_mma_tile<false>(g_comb, Wo, bo, out,
                         blockIdx.y*BM, blockIdx.x*BN, (4*DM)/BK, 4*DM, DM, DM, 1.f);
}

// ---------------- block reductions ----------------
__device__ __forceinline__ float blockReduceMax(float v, float* red) {
    int tid = threadIdx.x;
    red[tid] = v;
    __syncthreads();
    #pragma unroll
    for (int s = 128; s >= 1; s >>= 1) {
        if (tid < s) red[tid] = fmaxf(red[tid], red[tid + s]);
        __syncthreads();
    }
    float r = red[0];
    __syncthreads();
    return r;
}
__device__ __forceinline__ float blockReduceSum(float v, float* red) {
    int tid = threadIdx.x;
    red[tid] = v;
    __syncthreads();
    #pragma unroll
    for (int s = 128; s >= 1; s >>= 1) {
        if (tid < s) red[tid] = red[tid] + red[tid + s];
        __syncthreads();
    }
    float r = red[0];
    __syncthreads();
    return r;
}

// ---------------- masked softmax for all 4 rates + avg attention ----------------
__global__ __launch_bounds__(256) void softmax_kernel(float* __restrict__ avg_out)
{
    __shared__ float srow[SQ];
    __shared__ float avgs[SQ];
    __shared__ float red[256];

    int i = blockIdx.x;
    int b = blockIdx.y;
    int tid = threadIdx.x;

    const float* sc = &g_scores[((long)b*SQ + i) * SQ];
    for (int j = tid; j <= i; j += 256) srow[j] = sc[j];
    for (int j = tid; j < SQ; j += 256) avgs[j] = 0.f;
    __syncthreads();

    #pragma unroll
    for (int rr = 0; rr < 4; rr++) {
        const int rate = 1 << rr;
        const int Sr = SQ >> rr;
        float* attn;
        if (rr == 0)      attn = g_attn1;
        else if (rr == 1) attn = g_attn2;
        else if (rr == 2) attn = g_attn4;
        else              attn = g_attn8;

        int count = i / rate + 1;

        float mx = -1e30f;
        for (int m = tid; m < count; m += 256) mx = fmaxf(mx, srow[m*rate]);
        mx = blockReduceMax(mx, red);

        float sum = 0.f;
        for (int m = tid; m < count; m += 256) sum += __expf(srow[m*rate] - mx);
        sum = blockReduceSum(sum, red);
        float inv = 1.0f / sum;

        float* arow = attn + ((long)b*SQ + i) * Sr;
        for (int m = tid; m < Sr; m += 256) {
            float v = 0.f;
            if (m < count) {
                v = __expf(srow[m*rate] - mx) * inv;
                avgs[m*rate] += 0.25f * v;
            }
            arow[m] = v;
        }
        __syncthreads();
    }

    float* out = avg_out + ((long)b*SQ + i) * SQ;
    for (int j = tid; j < SQ; j += 256) out[j] = (j <= i) ? avgs[j] : 0.f;
}

// ---------------- launch ----------------
extern "C" void kernel_launch(void* const* d_in, const int* in_sizes, int n_in,
                              void* d_out, int out_size) {
    const float* x  = (const float*)d_in[0];
    const float* Wq = (const float*)d_in[1];
    const float* bq = (const float*)d_in[2];
    const float* Wk = (const float*)d_in[3];
    const float* bk = (const float*)d_in[4];
    const float* Wv = (const float*)d_in[5];
    const float* bv = (const float*)d_in[6];
    const float* Wr = (const float*)d_in[7];
    const float* br = (const float*)d_in[8];
    const float* Wo = (const float*)d_in[9];
    const float* bo = (const float*)d_in[10];
    float* out = (float*)d_out;

    dim3 blk(256);

    // QKV projections (fused: z picks W/bias/out)
    k_qkv<<<dim3(DM/BN, MS/BM, 3), blk>>>(x, Wq, bq, Wk, bk, Wv, bv);

    // scores = Q @ K^T / sqrt(D), lower-triangle tiles only
    k_scores<<<dim3(SQ/BN, SQ/BM, NB), blk>>>();

    // masked softmax for all rates + avg attention
    softmax_kernel<<<dim3(SQ, NB), blk>>>(out + (long)MS*DM);

    // ctx[r] = attn_c[r] @ V(dilated rows), all rates+batches in one launch
    k_attnv<<<dim3(DM/BN, SQ/BM, 4*NB), blk>>>();

    // per-rate projections into strided columns of combined (fused over rates)
    k_rproj<<<dim3(DM/BN, MS/BM, 4), blk>>>(Wr, br);

    // output = combined @ Wo + bo
    k_final<<<dim3(DM/BN, MS/BM, 1), blk>>>(Wo, bo, out);
}

// round 3
// speedup vs baseline: 3.0059x; 1.5368x over previous
#include <cuda_runtime.h>
#include <cstdint>

#define SQ 2048
#define DM 512
#define NB 2
#define MS (NB*SQ)   // 4096

#define BM 128
#define BN 128
#define BK 16
#define APITCH 20     // [row][k] pitched layout (A and NT-B)
#define BPITCH 136    // [k][n] pitched layout (NN-B)
#define STGF (BM*APITCH)   // floats per stage buffer (2560)

// ---------------- scratch (static device globals; no allocation) ----------------
__device__ float g_xq[MS*DM];
__device__ float g_wqq[DM*DM];
__device__ float g_wkq[DM*DM];
__device__ float g_wvq[DM*DM];
__device__ float g_wrq[4*DM*DM];
__device__ float g_woq[4*DM*DM];
__device__ float g_weff[4*DM*DM];   // [2048 x 512] stacked row blocks
__device__ float g_beff[DM];
__device__ float g_Q[MS*DM];
__device__ float g_K[MS*DM];
__device__ float g_V[MS*DM];
__device__ float g_scores[(long)NB*SQ*SQ];
__device__ float g_attn1[(long)NB*SQ*SQ];
__device__ float g_attn2[(long)NB*SQ*(SQ/2)];
__device__ float g_attn4[(long)NB*SQ*(SQ/4)];
__device__ float g_attn8[(long)NB*SQ*(SQ/8)];
__device__ float g_comb[(long)MS*4*DM];  // ctx concat [4096 x 2048]

__device__ __forceinline__ uint32_t f2tf(float f) {
    uint32_t u;
    asm("cvt.rna.tf32.f32 %0, %1;" : "=r"(u) : "f"(f));
    return u;
}
__device__ __forceinline__ float tfround(float f) { return __uint_as_float(f2tf(f)); }

__device__ __forceinline__ void mma8(float* c, const uint32_t* a, const uint32_t* b) {
    asm volatile(
        "mma.sync.aligned.m16n8k8.row.col.f32.tf32.tf32.f32 "
        "{%0,%1,%2,%3}, {%4,%5,%6,%7}, {%8,%9}, {%0,%1,%2,%3};"
        : "+f"(c[0]), "+f"(c[1]), "+f"(c[2]), "+f"(c[3])
        : "r"(a[0]), "r"(a[1]), "r"(a[2]), "r"(a[3]), "r"(b[0]), "r"(b[1]));
}

__device__ __forceinline__ void cpa16(uint32_t saddr, const float* g) {
    asm volatile("cp.async.cg.shared.global [%0], [%1], 16;" :: "r"(saddr), "l"(g));
}
__device__ __forceinline__ void cp_commit() { asm volatile("cp.async.commit_group;"); }
__device__ __forceinline__ void cp_wait1()  { asm volatile("cp.async.wait_group 1;"); }

// ---------------- 128x128x(16*ktiles) tf32 MMA core, cp.async double-buffered ----------------
// Inputs must already be tf32-rounded fp32.
// NT=false: B row-major [K,N], physical row step ldb (supports dilated V rows).
// NT=true : B is [N,K] row-major (scores K-matrix); stored [n][k] pitched in smem.
// ROUND: round epilogue result (incl. bias) to tf32 before store.
template<bool NT, bool ROUND>
__device__ __forceinline__ void gemm_core(
    const float* __restrict__ A, const float* __restrict__ B,
    const float* __restrict__ bias, float* __restrict__ C,
    int i0, int n0, int ktiles, int lda, int ldb, int ldc, float alpha)
{
    __shared__ float As[2][STGF];
    __shared__ float Bs[2][STGF];

    const int tid  = threadIdx.x;
    const int lane = tid & 31;
    const int wid  = tid >> 5;
    const int wm   = wid >> 2;        // 0..1
    const int wn   = wid & 3;         // 0..3
    const int gq   = lane >> 2;       // 0..7
    const int tg   = lane & 3;        // 0..3

    const uint32_t a_base = (uint32_t)__cvta_generic_to_shared(&As[0][0]);
    const uint32_t b_base = (uint32_t)__cvta_generic_to_shared(&Bs[0][0]);

    float acc[4][4][4];
    #pragma unroll
    for (int a = 0; a < 4; a++)
        #pragma unroll
        for (int b2 = 0; b2 < 4; b2++)
            #pragma unroll
            for (int c = 0; c < 4; c++) acc[a][b2][c] = 0.f;

    // issue stage st loads for k-tile kt
    auto issue = [&](int kt, int st) {
        const int k0 = kt * BK;
        const uint32_t ab = a_base + (uint32_t)st * STGF * 4u;
        const uint32_t bb = b_base + (uint32_t)st * STGF * 4u;
        #pragma unroll
        for (int j = 0; j < 2; j++) {
            int e = tid + j * 256;
            int m = e >> 2, kq = (e & 3) * 4;
            cpa16(ab + (uint32_t)(m * APITCH + kq) * 4u,
                  &A[(long)(i0 + m) * lda + k0 + kq]);
            if (NT) {
                cpa16(bb + (uint32_t)(m * APITCH + kq) * 4u,
                      &B[(long)(n0 + m) * ldb + k0 + kq]);
            } else {
                int kr = e >> 5, nq = (e & 31) * 4;
                cpa16(bb + (uint32_t)(kr * BPITCH + nq) * 4u,
                      &B[(long)(k0 + kr) * ldb + n0 + nq]);
            }
        }
    };

    issue(0, 0);
    cp_commit();

    for (int kt = 0; kt < ktiles; kt++) {
        const int cur = kt & 1;
        if (kt + 1 < ktiles) issue(kt + 1, cur ^ 1);
        cp_commit();           // (possibly empty) group keeps wait bookkeeping uniform
        cp_wait1();            // stage kt complete
        __syncthreads();

        const uint32_t* Au = (const uint32_t*)As[cur];
        const uint32_t* Bu = (const uint32_t*)Bs[cur];
        #pragma unroll
        for (int ks = 0; ks < 2; ks++) {
            uint32_t af[4][4], bf[4][2];
            #pragma unroll
            for (int mt = 0; mt < 4; mt++) {
                int mr = wm*64 + mt*16;
                af[mt][0] = Au[(mr+gq  )*APITCH + ks*8 + tg    ];
                af[mt][1] = Au[(mr+gq+8)*APITCH + ks*8 + tg    ];
                af[mt][2] = Au[(mr+gq  )*APITCH + ks*8 + tg + 4];
                af[mt][3] = Au[(mr+gq+8)*APITCH + ks*8 + tg + 4];
            }
            #pragma unroll
            for (int nt = 0; nt < 4; nt++) {
                int nc = wn*32 + nt*8;
                if (NT) {
                    bf[nt][0] = Bu[(nc+gq)*APITCH + ks*8 + tg    ];
                    bf[nt][1] = Bu[(nc+gq)*APITCH + ks*8 + tg + 4];
                } else {
                    bf[nt][0] = Bu[(ks*8+tg  )*BPITCH + nc + gq];
                    bf[nt][1] = Bu[(ks*8+tg+4)*BPITCH + nc + gq];
                }
            }
            #pragma unroll
            for (int mt = 0; mt < 4; mt++)
                #pragma unroll
                for (int nt = 0; nt < 4; nt++)
                    mma8(acc[mt][nt], af[mt], bf[nt]);
        }
        __syncthreads();
    }

    // ---- epilogue ----
    #pragma unroll
    for (int nt = 0; nt < 4; nt++) {
        int col = n0 + wn*32 + nt*8 + tg*2;
        float bx = 0.f, by = 0.f;
        if (bias) { bx = bias[col]; by = bias[col+1]; }
        #pragma unroll
        for (int mt = 0; mt < 4; mt++) {
            int row = i0 + wm*64 + mt*16 + gq;
            const float* c = acc[mt][nt];
            float v0 = c[0]*alpha + bx, v1 = c[1]*alpha + by;
            float v2 = c[2]*alpha + bx, v3 = c[3]*alpha + by;
            if (ROUND) { v0 = tfround(v0); v1 = tfround(v1); v2 = tfround(v2); v3 = tfround(v3); }
            *(float2*)&C[(long)row*ldc + col]     = make_float2(v0, v1);
            *(float2*)&C[(long)(row+8)*ldc + col] = make_float2(v2, v3);
        }
    }
}

// ---------------- kernels ----------------
__global__ __launch_bounds__(256) void k_quant4(const float* __restrict__ s,
                                                float* __restrict__ d, int n4) {
    int i = blockIdx.x * 256 + threadIdx.x;
    if (i < n4) {
        float4 v = ((const float4*)s)[i];
        v.x = tfround(v.x); v.y = tfround(v.y); v.z = tfround(v.z); v.w = tfround(v.w);
        ((float4*)d)[i] = v;
    }
}

__global__ __launch_bounds__(256) void k_beff(const float* __restrict__ br,
                                              const float* __restrict__ Wo,
                                              const float* __restrict__ bo) {
    int n = blockIdx.x * 256 + threadIdx.x;   // grid 2 -> 512
    float s = bo[n];
    for (int k = 0; k < 4*DM; k++) s += br[k] * Wo[(long)k*DM + n];
    g_beff[n] = s;
}

__global__ __launch_bounds__(256,2) void k_weff() {
    int r = blockIdx.z;
    gemm_core<false,true>(g_wrq + (long)r*DM*DM, g_woq + (long)r*DM*DM, nullptr,
                          g_weff + (long)r*DM*DM,
                          blockIdx.y*BM, blockIdx.x*BN, DM/BK, DM, DM, DM, 1.f);
}

__global__ __launch_bounds__(256,2) void k_qkv() {
    int z = blockIdx.z;
    const float* W = (z == 0) ? g_wqq : (z == 1) ? g_wkq : g_wvq;
    float* O = (z == 0) ? g_Q : (z == 1) ? g_K : g_V;
    gemm_core<false,true>(g_xq, W, nullptr, O, blockIdx.y*BM, blockIdx.x*BN,
                          DM/BK, DM, DM, DM, 1.f);
}
// bias for qkv is zero in setup but must be general: pass the real biases
__global__ __launch_bounds__(256,2) void k_qkv_b(
    const float* __restrict__ bq, const float* __restrict__ bk, const float* __restrict__ bv) {
    int z = blockIdx.z;
    const float* W = (z == 0) ? g_wqq : (z == 1) ? g_wkq : g_wvq;
    const float* b = (z == 0) ? bq : (z == 1) ? bk : bv;
    float* O = (z == 0) ? g_Q : (z == 1) ? g_K : g_V;
    gemm_core<false,true>(g_xq, W, b, O, blockIdx.y*BM, blockIdx.x*BN,
                          DM/BK, DM, DM, DM, 1.f);
}

__global__ __launch_bounds__(256,2) void k_scores() {
    int i0 = blockIdx.y * BM;
    int j0 = blockIdx.x * BN;
    if (j0 > i0 + (BM-1)) return;   // fully-masked tile, never read
    int b = blockIdx.z;
    gemm_core<true,false>(g_Q + (long)b*SQ*DM, g_K + (long)b*SQ*DM, nullptr,
                          g_scores + (long)b*SQ*SQ, i0, j0,
                          DM/BK, DM, DM, SQ, 0.044194173824159216f);
}

__global__ __launch_bounds__(256,2) void k_attnv() {
    int z = blockIdx.z;
    int r = z & 3, b = z >> 2;
    int rate = 1 << r, Sr = SQ >> r;
    const float* attn = ((r==0) ? g_attn1 : (r==1) ? g_attn2 : (r==2) ? g_attn4 : g_attn8)
                        + (long)b*SQ*Sr;
    const float* V = g_V + (long)b*SQ*DM;
    float* Cc = g_comb + (long)b*SQ*4*DM + r*DM;   // concat layout [4096 x 2048]
    int i0 = blockIdx.y * BM;
    int kmax = (i0 + BM - 1)/rate + 1;             // multiple of 16 by construction
    if (kmax > Sr) kmax = Sr;
    gemm_core<false,true>(attn, V, nullptr, Cc, i0, blockIdx.x*BN,
                          kmax/BK, Sr, rate*DM, 4*DM, 1.f);
}

__global__ __launch_bounds__(256,2) void k_final(float* __restrict__ out) {
    gemm_core<false,false>(g_comb, g_weff, g_beff, out,
                           blockIdx.y*BM, blockIdx.x*BN, (4*DM)/BK, 4*DM, DM, DM, 1.f);
}

// ---------------- block reductions ----------------
__device__ __forceinline__ float blockReduceMax(float v, float* red) {
    int tid = threadIdx.x;
    red[tid] = v;
    __syncthreads();
    #pragma unroll
    for (int s = 128; s >= 1; s >>= 1) {
        if (tid < s) red[tid] = fmaxf(red[tid], red[tid + s]);
        __syncthreads();
    }
    float r = red[0];
    __syncthreads();
    return r;
}
__device__ __forceinline__ float blockReduceSum(float v, float* red) {
    int tid = threadIdx.x;
    red[tid] = v;
    __syncthreads();
    #pragma unroll
    for (int s = 128; s >= 1; s >>= 1) {
        if (tid < s) red[tid] = red[tid] + red[tid + s];
        __syncthreads();
    }
    float r = red[0];
    __syncthreads();
    return r;
}

// ---------------- masked softmax for all 4 rates + avg attention ----------------
__global__ __launch_bounds__(256) void softmax_kernel(float* __restrict__ avg_out)
{
    __shared__ float srow[SQ];
    __shared__ float avgs[SQ];
    __shared__ float red[256];

    int i = blockIdx.x;
    int b = blockIdx.y;
    int tid = threadIdx.x;

    const float* sc = &g_scores[((long)b*SQ + i) * SQ];
    for (int j = tid; j <= i; j += 256) srow[j] = sc[j];
    for (int j = tid; j < SQ; j += 256) avgs[j] = 0.f;
    __syncthreads();

    #pragma unroll
    for (int rr = 0; rr < 4; rr++) {
        const int rate = 1 << rr;
        const int Sr = SQ >> rr;
        float* attn;
        if (rr == 0)      attn = g_attn1;
        else if (rr == 1) attn = g_attn2;
        else if (rr == 2) attn = g_attn4;
        else              attn = g_attn8;

        int count = i / rate + 1;

        float mx = -1e30f;
        for (int m = tid; m < count; m += 256) mx = fmaxf(mx, srow[m*rate]);
        mx = blockReduceMax(mx, red);

        float sum = 0.f;
        for (int m = tid; m < count; m += 256) sum += __expf(srow[m*rate] - mx);
        sum = blockReduceSum(sum, red);
        float inv = 1.0f / sum;

        float* arow = attn + ((long)b*SQ + i) * Sr;
        for (int m = tid; m < Sr; m += 256) {
            float v = 0.f;
            if (m < count) {
                v = __expf(srow[m*rate] - mx) * inv;
                avgs[m*rate] += 0.25f * v;
            }
            arow[m] = tfround(v);   // GEMM input: pre-round to tf32
        }
        __syncthreads();
    }

    float* out = avg_out + ((long)b*SQ + i) * SQ;
    for (int j = tid; j < SQ; j += 256) out[j] = (j <= i) ? avgs[j] : 0.f;
}

// ---------------- launch ----------------
extern "C" void kernel_launch(void* const* d_in, const int* in_sizes, int n_in,
                              void* d_out, int out_size) {
    const float* x  = (const float*)d_in[0];
    const float* Wq = (const float*)d_in[1];
    const float* bq = (const float*)d_in[2];
    const float* Wk = (const float*)d_in[3];
    const float* bk = (const float*)d_in[4];
    const float* Wv = (const float*)d_in[5];
    const float* bv = (const float*)d_in[6];
    const float* Wr = (const float*)d_in[7];
    const float* br = (const float*)d_in[8];
    const float* Wo = (const float*)d_in[9];
    const float* bo = (const float*)d_in[10];
    float* out = (float*)d_out;

    float *xq, *wqq, *wkq, *wvq, *wrq, *woq;
    cudaGetSymbolAddress((void**)&xq,  g_xq);
    cudaGetSymbolAddress((void**)&wqq, g_wqq);
    cudaGetSymbolAddress((void**)&wkq, g_wkq);
    cudaGetSymbolAddress((void**)&wvq, g_wvq);
    cudaGetSymbolAddress((void**)&wrq, g_wrq);
    cudaGetSymbolAddress((void**)&woq, g_woq);

    dim3 blk(256);

    // quantize all GEMM inputs to tf32-rounded fp32
    k_quant4<<<(MS*DM/4 + 255)/256, blk>>>(x,  xq,  MS*DM/4);
    k_quant4<<<(DM*DM/4 + 255)/256, blk>>>(Wq, wqq, DM*DM/4);
    k_quant4<<<(DM*DM/4 + 255)/256, blk>>>(Wk, wkq, DM*DM/4);
    k_quant4<<<(DM*DM/4 + 255)/256, blk>>>(Wv, wvq, DM*DM/4);
    k_quant4<<<(4*DM*DM/4 + 255)/256, blk>>>(Wr, wrq, 4*DM*DM/4);
    k_quant4<<<(4*DM*DM/4 + 255)/256, blk>>>(Wo, woq, 4*DM*DM/4);

    // fused output weights: Weff[r] = Wr[r] @ Wo_r ; beff = br_flat @ Wo + bo
    k_weff<<<dim3(DM/BN, DM/BM, 4), blk>>>();
    k_beff<<<dim3(2), blk>>>(br, Wo, bo);

    // QKV projections
    k_qkv_b<<<dim3(DM/BN, MS/BM, 3), blk>>>(bq, bk, bv);

    // scores = Q @ K^T / sqrt(D), lower-triangle tiles only
    k_scores<<<dim3(SQ/BN, SQ/BM, NB), blk>>>();

    // masked softmax for all rates + avg attention
    softmax_kernel<<<dim3(SQ, NB), blk>>>(out + (long)MS*DM);

    // ctx[r] = attn_c[r] @ V(dilated rows) -> concat buffer
    k_attnv<<<dim3(DM/BN, SQ/BM, 4*NB), blk>>>();

    // output = ctxcat @ Weff + beff
    k_final<<<dim3(DM/BN, MS/BM, 1), blk>>>(out);
}

// round 4
// speedup vs baseline: 4.4435x; 1.4782x over previous
#include <cuda_runtime.h>
#include <cuda_fp16.h>
#include <cstdint>

#define SQ 2048
#define DM 512
#define NB 2
#define MS (NB*SQ)   // 4096

#define BM 128
#define BN 128
#define BK 32
#define APITCH 40     // halves; [row][k] layout (A, NT-B): 80B row stride, ldmatrix conflict-free
#define BPITCH 136    // halves; [k][n] layout (NN-B): 272B row stride, conflict-free
#define ASTG (BM*APITCH)          // 5120 halves per stage
#define BSTG 5120                 // max(32*136=4352, 128*40=5120)

// ---------------- scratch (static device globals; no allocation) ----------------
__device__ __half g_xh[MS*DM];
__device__ __half g_wqh[DM*DM];
__device__ __half g_wkh[DM*DM];
__device__ __half g_wvh[DM*DM];
__device__ __half g_wrh[4*DM*DM];
__device__ __half g_woh[4*DM*DM];
__device__ __half g_weff[4*DM*DM];   // [2048 x 512]
__device__ float  g_beff[DM];
__device__ __half g_Q[MS*DM];
__device__ __half g_K[MS*DM];
__device__ __half g_V[MS*DM];
__device__ float  g_scores[(long)NB*SQ*SQ];
__device__ __half g_attn1[(long)NB*SQ*SQ];
__device__ __half g_attn2[(long)NB*SQ*(SQ/2)];
__device__ __half g_attn4[(long)NB*SQ*(SQ/4)];
__device__ __half g_attn8[(long)NB*SQ*(SQ/8)];
__device__ __half g_comb[(long)MS*4*DM];  // ctx concat [4096 x 2048]

// ---------------- PTX helpers ----------------
__device__ __forceinline__ void mma16(float* c, const uint32_t* a, const uint32_t* b) {
    asm volatile(
        "mma.sync.aligned.m16n8k16.row.col.f32.f16.f16.f32 "
        "{%0,%1,%2,%3}, {%4,%5,%6,%7}, {%8,%9}, {%0,%1,%2,%3};"
        : "+f"(c[0]), "+f"(c[1]), "+f"(c[2]), "+f"(c[3])
        : "r"(a[0]), "r"(a[1]), "r"(a[2]), "r"(a[3]), "r"(b[0]), "r"(b[1]));
}
__device__ __forceinline__ void ldsm4(uint32_t* r, uint32_t addr) {
    asm volatile("ldmatrix.sync.aligned.m8n8.x4.shared.b16 {%0,%1,%2,%3}, [%4];"
                 : "=r"(r[0]), "=r"(r[1]), "=r"(r[2]), "=r"(r[3]) : "r"(addr));
}
__device__ __forceinline__ void ldsm4t(uint32_t* r, uint32_t addr) {
    asm volatile("ldmatrix.sync.aligned.m8n8.x4.trans.shared.b16 {%0,%1,%2,%3}, [%4];"
                 : "=r"(r[0]), "=r"(r[1]), "=r"(r[2]), "=r"(r[3]) : "r"(addr));
}
__device__ __forceinline__ void cpa16(uint32_t saddr, const void* g) {
    asm volatile("cp.async.cg.shared.global [%0], [%1], 16;" :: "r"(saddr), "l"(g));
}
__device__ __forceinline__ void cp_commit() { asm volatile("cp.async.commit_group;"); }
__device__ __forceinline__ void cp_wait1()  { asm volatile("cp.async.wait_group 1;"); }

// ---------------- 128x128x(32*ktiles) fp16 MMA core ----------------
// NT=false: B row-major [K,N], physical row step ldb halves (supports dilated V rows).
// NT=true : B is [N,K] row-major (scores K-matrix); stored [n][k] in smem.
// HOUT: store half output; else fp32.
template<bool NT, bool HOUT>
__device__ __forceinline__ void gemm_core(
    const __half* __restrict__ A, const __half* __restrict__ B,
    const float* __restrict__ bias, void* __restrict__ Cv,
    int i0, int n0, int ktiles, int lda, int ldb, int ldc, float alpha)
{
    __shared__ __half As[2][ASTG];
    __shared__ __half Bs[2][BSTG];

    const int tid  = threadIdx.x;
    const int lane = tid & 31;
    const int wid  = tid >> 5;
    const int wm   = wid >> 2;        // 0..1
    const int wn   = wid & 3;         // 0..3
    const int gq   = lane >> 2;       // 0..7
    const int tg   = lane & 3;        // 0..3
    const int quad = lane >> 3;       // 0..3
    const int wthr = lane & 7;        // 0..7

    const uint32_t a_base = (uint32_t)__cvta_generic_to_shared(&As[0][0]);
    const uint32_t b_base = (uint32_t)__cvta_generic_to_shared(&Bs[0][0]);

    float acc[4][4][4];
    #pragma unroll
    for (int a = 0; a < 4; a++)
        #pragma unroll
        for (int b2 = 0; b2 < 4; b2++)
            #pragma unroll
            for (int c = 0; c < 4; c++) acc[a][b2][c] = 0.f;

    auto issue = [&](int kt, int st) {
        const int k0 = kt * BK;
        const uint32_t ab = a_base + (uint32_t)st * ASTG * 2u;
        const uint32_t bb = b_base + (uint32_t)st * BSTG * 2u;
        #pragma unroll
        for (int j = 0; j < 2; j++) {
            int e = tid + j * 256;
            int m = e >> 2, kq = (e & 3) * 8;
            cpa16(ab + (uint32_t)(m * APITCH + kq) * 2u,
                  &A[(long)(i0 + m) * lda + k0 + kq]);
            if (NT) {
                cpa16(bb + (uint32_t)(m * APITCH + kq) * 2u,
                      &B[(long)(n0 + m) * ldb + k0 + kq]);
            } else {
                int kr = e >> 4, nq = (e & 15) * 8;
                cpa16(bb + (uint32_t)(kr * BPITCH + nq) * 2u,
                      &B[(long)(k0 + kr) * ldb + n0 + nq]);
            }
        }
    };

    issue(0, 0);
    cp_commit();

    for (int kt = 0; kt < ktiles; kt++) {
        const int cur = kt & 1;
        if (kt + 1 < ktiles) issue(kt + 1, cur ^ 1);
        cp_commit();
        cp_wait1();
        __syncthreads();

        const uint32_t ab = a_base + (uint32_t)cur * ASTG * 2u;
        const uint32_t bb = b_base + (uint32_t)cur * BSTG * 2u;

        #pragma unroll
        for (int ks = 0; ks < 2; ks++) {
            uint32_t af[4][4], bf[4][2];
            #pragma unroll
            for (int mt = 0; mt < 4; mt++) {
                int arow = wm*64 + mt*16 + wthr + (quad & 1) * 8;
                int acol = ks*16 + (quad >> 1) * 8;
                ldsm4(af[mt], ab + (uint32_t)(arow * APITCH + acol) * 2u);
            }
            #pragma unroll
            for (int nh = 0; nh < 2; nh++) {
                int nc = wn*32 + nh*16;
                uint32_t r[4];
                if (NT) {
                    int brow = nc + wthr + (quad >> 1) * 8;
                    int bcol = ks*16 + (quad & 1) * 8;
                    ldsm4(r, bb + (uint32_t)(brow * APITCH + bcol) * 2u);
                } else {
                    int brow = ks*16 + wthr + (quad & 1) * 8;
                    int bcol = nc + (quad >> 1) * 8;
                    ldsm4t(r, bb + (uint32_t)(brow * BPITCH + bcol) * 2u);
                }
                bf[nh*2+0][0] = r[0]; bf[nh*2+0][1] = r[1];
                bf[nh*2+1][0] = r[2]; bf[nh*2+1][1] = r[3];
            }
            #pragma unroll
            for (int mt = 0; mt < 4; mt++)
                #pragma unroll
                for (int nt = 0; nt < 4; nt++)
                    mma16(acc[mt][nt], af[mt], bf[nt]);
        }
        __syncthreads();
    }

    // ---- epilogue ----
    #pragma unroll
    for (int nt = 0; nt < 4; nt++) {
        int col = n0 + wn*32 + nt*8 + tg*2;
        float bx = 0.f, by = 0.f;
        if (bias) { bx = bias[col]; by = bias[col+1]; }
        #pragma unroll
        for (int mt = 0; mt < 4; mt++) {
            int row = i0 + wm*64 + mt*16 + gq;
            const float* c = acc[mt][nt];
            float v0 = c[0]*alpha + bx, v1 = c[1]*alpha + by;
            float v2 = c[2]*alpha + bx, v3 = c[3]*alpha + by;
            if (HOUT) {
                __half* C = (__half*)Cv;
                *(__half2*)&C[(long)row*ldc + col]     = __floats2half2_rn(v0, v1);
                *(__half2*)&C[(long)(row+8)*ldc + col] = __floats2half2_rn(v2, v3);
            } else {
                float* C = (float*)Cv;
                *(float2*)&C[(long)row*ldc + col]     = make_float2(v0, v1);
                *(float2*)&C[(long)(row+8)*ldc + col] = make_float2(v2, v3);
            }
        }
    }
}

// ---------------- kernels ----------------
__global__ __launch_bounds__(256) void k_tohalf(const float* __restrict__ s,
                                                __half* __restrict__ d, int n4) {
    int i = blockIdx.x * 256 + threadIdx.x;
    if (i < n4) {
        float4 v = ((const float4*)s)[i];
        __half2 h0 = __floats2half2_rn(v.x, v.y);
        __half2 h1 = __floats2half2_rn(v.z, v.w);
        *(__half2*)&d[i*4]   = h0;
        *(__half2*)&d[i*4+2] = h1;
    }
}

__global__ __launch_bounds__(256) void k_beff(const float* __restrict__ br,
                                              const float* __restrict__ Wo,
                                              const float* __restrict__ bo) {
    int n = blockIdx.x * 256 + threadIdx.x;
    float s = bo[n];
    for (int k = 0; k < 4*DM; k++) s += br[k] * Wo[(long)k*DM + n];
    g_beff[n] = s;
}

__global__ __launch_bounds__(256,2) void k_weff() {
    int r = blockIdx.z;
    gemm_core<false,true>(g_wrh + (long)r*DM*DM, g_woh + (long)r*DM*DM, nullptr,
                          g_weff + (long)r*DM*DM,
                          blockIdx.y*BM, blockIdx.x*BN, DM/BK, DM, DM, DM, 1.f);
}

__global__ __launch_bounds__(256,2) void k_qkv_b(
    const float* __restrict__ bq, const float* __restrict__ bk, const float* __restrict__ bv) {
    int z = blockIdx.z;
    const __half* W = (z == 0) ? g_wqh : (z == 1) ? g_wkh : g_wvh;
    const float* b = (z == 0) ? bq : (z == 1) ? bk : bv;
    __half* O = (z == 0) ? g_Q : (z == 1) ? g_K : g_V;
    gemm_core<false,true>(g_xh, W, b, O, blockIdx.y*BM, blockIdx.x*BN,
                          DM/BK, DM, DM, DM, 1.f);
}

__global__ __launch_bounds__(256,2) void k_scores() {
    int i0 = blockIdx.y * BM;
    int j0 = blockIdx.x * BN;
    if (j0 > i0 + (BM-1)) return;   // fully-masked tile, never read
    int b = blockIdx.z;
    gemm_core<true,false>(g_Q + (long)b*SQ*DM, g_K + (long)b*SQ*DM, nullptr,
                          g_scores + (long)b*SQ*SQ, i0, j0,
                          DM/BK, DM, DM, SQ, 0.044194173824159216f);
}

__global__ __launch_bounds__(256,2) void k_attnv() {
    int z = blockIdx.z;
    int r = z & 3, b = z >> 2;
    int rate = 1 << r, Sr = SQ >> r;
    const __half* attn = ((r==0) ? g_attn1 : (r==1) ? g_attn2 : (r==2) ? g_attn4 : g_attn8)
                        + (long)b*SQ*Sr;
    const __half* V = g_V + (long)b*SQ*DM;
    __half* Cc = g_comb + (long)b*SQ*4*DM + r*DM;   // concat layout [4096 x 2048]
    int i0 = blockIdx.y * BM;
    int kmax = (i0 + BM - 1)/rate + 1;
    if (kmax > Sr) kmax = Sr;
    int ktiles = (kmax + BK - 1) / BK;              // extra cols are zeros in attn
    gemm_core<false,true>(attn, V, nullptr, Cc, i0, blockIdx.x*BN,
                          ktiles, Sr, rate*DM, 4*DM, 1.f);
}

__global__ __launch_bounds__(256,2) void k_final(float* __restrict__ out) {
    gemm_core<false,false>(g_comb, g_weff, g_beff, out,
                           blockIdx.y*BM, blockIdx.x*BN, (4*DM)/BK, 4*DM, DM, DM, 1.f);
}

// ---------------- block reductions ----------------
__device__ __forceinline__ float blockReduceMax(float v, float* red) {
    int tid = threadIdx.x;
    red[tid] = v;
    __syncthreads();
    #pragma unroll
    for (int s = 128; s >= 1; s >>= 1) {
        if (tid < s) red[tid] = fmaxf(red[tid], red[tid + s]);
        __syncthreads();
    }
    float r = red[0];
    __syncthreads();
    return r;
}
__device__ __forceinline__ float blockReduceSum(float v, float* red) {
    int tid = threadIdx.x;
    red[tid] = v;
    __syncthreads();
    #pragma unroll
    for (int s = 128; s >= 1; s >>= 1) {
        if (tid < s) red[tid] = red[tid] + red[tid + s];
        __syncthreads();
    }
    float r = red[0];
    __syncthreads();
    return r;
}

// ---------------- masked softmax for all 4 rates + avg attention ----------------
__global__ __launch_bounds__(256) void softmax_kernel(float* __restrict__ avg_out)
{
    __shared__ float srow[SQ];
    __shared__ float avgs[SQ];
    __shared__ float red[256];

    int i = blockIdx.x;
    int b = blockIdx.y;
    int tid = threadIdx.x;

    const float* sc = &g_scores[((long)b*SQ + i) * SQ];
    for (int j = tid; j <= i; j += 256) srow[j] = sc[j];
    for (int j = tid; j < SQ; j += 256) avgs[j] = 0.f;
    __syncthreads();

    #pragma unroll
    for (int rr = 0; rr < 4; rr++) {
        const int rate = 1 << rr;
        const int Sr = SQ >> rr;
        __half* attn;
        if (rr == 0)      attn = g_attn1;
        else if (rr == 1) attn = g_attn2;
        else if (rr == 2) attn = g_attn4;
        else              attn = g_attn8;

        int count = i / rate + 1;

        float mx = -1e30f;
        for (int m = tid; m < count; m += 256) mx = fmaxf(mx, srow[m*rate]);
        mx = blockReduceMax(mx, red);

        float sum = 0.f;
        for (int m = tid; m < count; m += 256) sum += __expf(srow[m*rate] - mx);
        sum = blockReduceSum(sum, red);
        float inv = 1.0f / sum;

        __half* arow = attn + ((long)b*SQ + i) * Sr;
        for (int m = tid; m < Sr; m += 256) {
            float v = 0.f;
            if (m < count) {
                v = __expf(srow[m*rate] - mx) * inv;
                avgs[m*rate] += 0.25f * v;
            }
            arow[m] = __float2half_rn(v);
        }
        __syncthreads();
    }

    float* out = avg_out + ((long)b*SQ + i) * SQ;
    for (int j = tid; j < SQ; j += 256) out[j] = (j <= i) ? avgs[j] : 0.f;
}

// ---------------- launch ----------------
extern "C" void kernel_launch(void* const* d_in, const int* in_sizes, int n_in,
                              void* d_out, int out_size) {
    const float* x  = (const float*)d_in[0];
    const float* Wq = (const float*)d_in[1];
    const float* bq = (const float*)d_in[2];
    const float* Wk = (const float*)d_in[3];
    const float* bk = (const float*)d_in[4];
    const float* Wv = (const float*)d_in[5];
    const float* bv = (const float*)d_in[6];
    const float* Wr = (const float*)d_in[7];
    const float* br = (const float*)d_in[8];
    const float* Wo = (const float*)d_in[9];
    const float* bo = (const float*)d_in[10];
    float* out = (float*)d_out;

    __half *xh, *wqh, *wkh, *wvh, *wrh, *woh;
    cudaGetSymbolAddress((void**)&xh,  g_xh);
    cudaGetSymbolAddress((void**)&wqh, g_wqh);
    cudaGetSymbolAddress((void**)&wkh, g_wkh);
    cudaGetSymbolAddress((void**)&wvh, g_wvh);
    cudaGetSymbolAddress((void**)&wrh, g_wrh);
    cudaGetSymbolAddress((void**)&woh, g_woh);

    dim3 blk(256);

    // convert GEMM inputs to fp16
    k_tohalf<<<(MS*DM/4 + 255)/256, blk>>>(x,  xh,  MS*DM/4);
    k_tohalf<<<(DM*DM/4 + 255)/256, blk>>>(Wq, wqh, DM*DM/4);
    k_tohalf<<<(DM*DM/4 + 255)/256, blk>>>(Wk, wkh, DM*DM/4);
    k_tohalf<<<(DM*DM/4 + 255)/256, blk>>>(Wv, wvh, DM*DM/4);
    k_tohalf<<<(4*DM*DM/4 + 255)/256, blk>>>(Wr, wrh, 4*DM*DM/4);
    k_tohalf<<<(4*DM*DM/4 + 255)/256, blk>>>(Wo, woh, 4*DM*DM/4);

    // fused output weights: Weff[r] = Wr[r] @ Wo_r ; beff = br_flat @ Wo + bo
    k_weff<<<dim3(DM/BN, DM/BM, 4), blk>>>();
    k_beff<<<dim3(2), blk>>>(br, Wo, bo);

    // QKV projections
    k_qkv_b<<<dim3(DM/BN, MS/BM, 3), blk>>>(bq, bk, bv);

    // scores = Q @ K^T / sqrt(D), lower-triangle tiles only
    k_scores<<<dim3(SQ/BN, SQ/BM, NB), blk>>>();

    // masked softmax for all rates + avg attention
    softmax_kernel<<<dim3(SQ, NB), blk>>>(out + (long)MS*DM);

    // ctx[r] = attn_c[r] @ V(dilated rows) -> concat buffer
    k_attnv<<<dim3(DM/BN, SQ/BM, 4*NB), blk>>>();

    // output = ctxcat @ Weff + beff
    k_final<<<dim3(DM/BN, MS/BM, 1), blk>>>(out);
}

// round 5
// speedup vs baseline: 4.7007x; 1.0579x over previous
#include <cuda_runtime.h>
#include <cuda_fp16.h>
#include <cstdint>

#define SQ 2048
#define DM 512
#define NB 2
#define MS (NB*SQ)   // 4096

#define BM 128
#define BN 128
#define BK 32
#define APITCH 40     // halves; [row][k] layout (A, NT-B)
#define BPITCH 136    // halves; [k][n] layout (NN-B)
#define ASTG (BM*APITCH)          // 5120 halves per stage
#define BSTG 5120                 // max(32*136=4352, 128*40=5120)
#define NSTAGE 3
#define DSMEM (NSTAGE*(ASTG+BSTG)*2)   // 61440 bytes

// ---------------- scratch (static device globals; no allocation) ----------------
__device__ __half g_xh[MS*DM];
__device__ __half g_wqh[DM*DM];
__device__ __half g_wkh[DM*DM];
__device__ __half g_wvh[DM*DM];
__device__ __half g_wrh[4*DM*DM];
__device__ __half g_woh[4*DM*DM];
__device__ __half g_weff[4*DM*DM];   // [2048 x 512]
__device__ float  g_beff[DM];
__device__ __half g_Q[MS*DM];
__device__ __half g_K[MS*DM];
__device__ __half g_V[MS*DM];
__device__ float  g_scores[(long)NB*SQ*SQ];
__device__ __half g_attn1[(long)NB*SQ*SQ];
__device__ __half g_attn2[(long)NB*SQ*(SQ/2)];
__device__ __half g_attn4[(long)NB*SQ*(SQ/4)];
__device__ __half g_attn8[(long)NB*SQ*(SQ/8)];
__device__ __half g_comb[(long)MS*4*DM];  // ctx concat [4096 x 2048]

// ---------------- PTX helpers ----------------
__device__ __forceinline__ void mma16(float* c, const uint32_t* a, const uint32_t* b) {
    asm volatile(
        "mma.sync.aligned.m16n8k16.row.col.f32.f16.f16.f32 "
        "{%0,%1,%2,%3}, {%4,%5,%6,%7}, {%8,%9}, {%0,%1,%2,%3};"
        : "+f"(c[0]), "+f"(c[1]), "+f"(c[2]), "+f"(c[3])
        : "r"(a[0]), "r"(a[1]), "r"(a[2]), "r"(a[3]), "r"(b[0]), "r"(b[1]));
}
__device__ __forceinline__ void ldsm4(uint32_t* r, uint32_t addr) {
    asm volatile("ldmatrix.sync.aligned.m8n8.x4.shared.b16 {%0,%1,%2,%3}, [%4];"
                 : "=r"(r[0]), "=r"(r[1]), "=r"(r[2]), "=r"(r[3]) : "r"(addr));
}
__device__ __forceinline__ void ldsm4t(uint32_t* r, uint32_t addr) {
    asm volatile("ldmatrix.sync.aligned.m8n8.x4.trans.shared.b16 {%0,%1,%2,%3}, [%4];"
                 : "=r"(r[0]), "=r"(r[1]), "=r"(r[2]), "=r"(r[3]) : "r"(addr));
}
__device__ __forceinline__ void cpa16(uint32_t saddr, const void* g) {
    asm volatile("cp.async.cg.shared.global [%0], [%1], 16;" :: "r"(saddr), "l"(g));
}
__device__ __forceinline__ void cp_commit() { asm volatile("cp.async.commit_group;"); }
__device__ __forceinline__ void cp_wait1()  { asm volatile("cp.async.wait_group 1;"); }

// ---------------- 128x128x(32*ktiles) fp16 MMA core, 3-stage pipeline ----------------
// NT=false: B row-major [K,N], physical row step ldb halves (supports dilated V rows).
// NT=true : B is [N,K] row-major (scores K-matrix); stored [n][k] in smem.
// HOUT: store half output; else fp32.
template<bool NT, bool HOUT>
__device__ __forceinline__ void gemm_core(
    __half* dsm,
    const __half* __restrict__ A, const __half* __restrict__ B,
    const float* __restrict__ bias, void* __restrict__ Cv,
    int i0, int n0, int ktiles, int lda, int ldb, int ldc, float alpha)
{
    __half* As = dsm;
    __half* Bs = dsm + NSTAGE * ASTG;

    const int tid  = threadIdx.x;
    const int lane = tid & 31;
    const int wid  = tid >> 5;
    const int wm   = wid >> 2;        // 0..1
    const int wn   = wid & 3;         // 0..3
    const int gq   = lane >> 2;       // 0..7
    const int tg   = lane & 3;        // 0..3
    const int quad = lane >> 3;       // 0..3
    const int wthr = lane & 7;        // 0..7

    const uint32_t a_base = (uint32_t)__cvta_generic_to_shared(As);
    const uint32_t b_base = (uint32_t)__cvta_generic_to_shared(Bs);

    float acc[4][4][4];
    #pragma unroll
    for (int a = 0; a < 4; a++)
        #pragma unroll
        for (int b2 = 0; b2 < 4; b2++)
            #pragma unroll
            for (int c = 0; c < 4; c++) acc[a][b2][c] = 0.f;

    auto issue = [&](int kt, int st) {
        const int k0 = kt * BK;
        const uint32_t ab = a_base + (uint32_t)st * ASTG * 2u;
        const uint32_t bb = b_base + (uint32_t)st * BSTG * 2u;
        #pragma unroll
        for (int j = 0; j < 2; j++) {
            int e = tid + j * 256;
            int m = e >> 2, kq = (e & 3) * 8;
            cpa16(ab + (uint32_t)(m * APITCH + kq) * 2u,
                  &A[(long)(i0 + m) * lda + k0 + kq]);
            if (NT) {
                cpa16(bb + (uint32_t)(m * APITCH + kq) * 2u,
                      &B[(long)(n0 + m) * ldb + k0 + kq]);
            } else {
                int kr = e >> 4, nq = (e & 15) * 8;
                cpa16(bb + (uint32_t)(kr * BPITCH + nq) * 2u,
                      &B[(long)(k0 + kr) * ldb + n0 + nq]);
            }
        }
    };

    // prologue: stages 0 and 1
    issue(0, 0);
    cp_commit();
    if (ktiles > 1) issue(1, 1);
    cp_commit();

    int cur = 0;       // stage holding k-tile kt
    int wst = 2;       // stage to write k-tile kt+2
    for (int kt = 0; kt < ktiles; kt++) {
        cp_wait1();            // stage for kt complete (newest group may be pending)
        __syncthreads();       // all warps done with stage wst's previous contents

        if (kt + 2 < ktiles) issue(kt + 2, wst);
        cp_commit();           // uniform group accounting (possibly empty group)

        const uint32_t ab = a_base + (uint32_t)cur * ASTG * 2u;
        const uint32_t bb = b_base + (uint32_t)cur * BSTG * 2u;

        #pragma unroll
        for (int ks = 0; ks < 2; ks++) {
            uint32_t af[4][4], bf[4][2];
            #pragma unroll
            for (int mt = 0; mt < 4; mt++) {
                int arow = wm*64 + mt*16 + wthr + (quad & 1) * 8;
                int acol = ks*16 + (quad >> 1) * 8;
                ldsm4(af[mt], ab + (uint32_t)(arow * APITCH + acol) * 2u);
            }
            #pragma unroll
            for (int nh = 0; nh < 2; nh++) {
                int nc = wn*32 + nh*16;
                uint32_t r[4];
                if (NT) {
                    int brow = nc + wthr + (quad >> 1) * 8;
                    int bcol = ks*16 + (quad & 1) * 8;
                    ldsm4(r, bb + (uint32_t)(brow * APITCH + bcol) * 2u);
                } else {
                    int brow = ks*16 + wthr + (quad & 1) * 8;
                    int bcol = nc + (quad >> 1) * 8;
                    ldsm4t(r, bb + (uint32_t)(brow * BPITCH + bcol) * 2u);
                }
                bf[nh*2+0][0] = r[0]; bf[nh*2+0][1] = r[1];
                bf[nh*2+1][0] = r[2]; bf[nh*2+1][1] = r[3];
            }
            #pragma unroll
            for (int mt = 0; mt < 4; mt++)
                #pragma unroll
                for (int nt = 0; nt < 4; nt++)
                    mma16(acc[mt][nt], af[mt], bf[nt]);
        }

        cur = (cur + 1 == NSTAGE) ? 0 : cur + 1;
        wst = (wst + 1 == NSTAGE) ? 0 : wst + 1;
    }

    // ---- epilogue ----
    #pragma unroll
    for (int nt = 0; nt < 4; nt++) {
        int col = n0 + wn*32 + nt*8 + tg*2;
        float bx = 0.f, by = 0.f;
        if (bias) { bx = bias[col]; by = bias[col+1]; }
        #pragma unroll
        for (int mt = 0; mt < 4; mt++) {
            int row = i0 + wm*64 + mt*16 + gq;
            const float* c = acc[mt][nt];
            float v0 = c[0]*alpha + bx, v1 = c[1]*alpha + by;
            float v2 = c[2]*alpha + bx, v3 = c[3]*alpha + by;
            if (HOUT) {
                __half* C = (__half*)Cv;
                *(__half2*)&C[(long)row*ldc + col]     = __floats2half2_rn(v0, v1);
                *(__half2*)&C[(long)(row+8)*ldc + col] = __floats2half2_rn(v2, v3);
            } else {
                float* C = (float*)Cv;
                *(float2*)&C[(long)row*ldc + col]     = make_float2(v0, v1);
                *(float2*)&C[(long)(row+8)*ldc + col] = make_float2(v2, v3);
            }
        }
    }
}

// ---------------- kernels ----------------
__global__ __launch_bounds__(256) void k_tohalf(const float* __restrict__ s,
                                                __half* __restrict__ d, int n4) {
    int i = blockIdx.x * 256 + threadIdx.x;
    if (i < n4) {
        float4 v = ((const float4*)s)[i];
        __half2 h0 = __floats2half2_rn(v.x, v.y);
        __half2 h1 = __floats2half2_rn(v.z, v.w);
        *(__half2*)&d[i*4]   = h0;
        *(__half2*)&d[i*4+2] = h1;
    }
}

__global__ __launch_bounds__(256) void k_beff(const float* __restrict__ br,
                                              const float* __restrict__ Wo,
                                              const float* __restrict__ bo) {
    int n = blockIdx.x * 256 + threadIdx.x;
    float s = bo[n];
    for (int k = 0; k < 4*DM; k++) s += br[k] * Wo[(long)k*DM + n];
    g_beff[n] = s;
}

__global__ __launch_bounds__(256,2) void k_weff() {
    extern __shared__ __half dsm[];
    int r = blockIdx.z;
    gemm_core<false,true>(dsm, g_wrh + (long)r*DM*DM, g_woh + (long)r*DM*DM, nullptr,
                          g_weff + (long)r*DM*DM,
                          blockIdx.y*BM, blockIdx.x*BN, DM/BK, DM, DM, DM, 1.f);
}

__global__ __launch_bounds__(256,2) void k_qkv_b(
    const float* __restrict__ bq, const float* __restrict__ bk, const float* __restrict__ bv) {
    extern __shared__ __half dsm[];
    int z = blockIdx.z;
    const __half* W = (z == 0) ? g_wqh : (z == 1) ? g_wkh : g_wvh;
    const float* b = (z == 0) ? bq : (z == 1) ? bk : bv;
    __half* O = (z == 0) ? g_Q : (z == 1) ? g_K : g_V;
    gemm_core<false,true>(dsm, g_xh, W, b, O, blockIdx.y*BM, blockIdx.x*BN,
                          DM/BK, DM, DM, DM, 1.f);
}

__global__ __launch_bounds__(256,2) void k_scores() {
    extern __shared__ __half dsm[];
    int i0 = blockIdx.y * BM;
    int j0 = blockIdx.x * BN;
    if (j0 > i0 + (BM-1)) return;   // fully-masked tile, never read
    int b = blockIdx.z;
    gemm_core<true,false>(dsm, g_Q + (long)b*SQ*DM, g_K + (long)b*SQ*DM, nullptr,
                          g_scores + (long)b*SQ*SQ, i0, j0,
                          DM/BK, DM, DM, SQ, 0.044194173824159216f);
}

__global__ __launch_bounds__(256,2) void k_attnv() {
    extern __shared__ __half dsm[];
    int z = blockIdx.z;
    int r = z & 3, b = z >> 2;
    int rate = 1 << r, Sr = SQ >> r;
    const __half* attn = ((r==0) ? g_attn1 : (r==1) ? g_attn2 : (r==2) ? g_attn4 : g_attn8)
                        + (long)b*SQ*Sr;
    const __half* V = g_V + (long)b*SQ*DM;
    __half* Cc = g_comb + (long)b*SQ*4*DM + r*DM;   // concat layout [4096 x 2048]
    int i0 = blockIdx.y * BM;
    int kmax = (i0 + BM - 1)/rate + 1;
    if (kmax > Sr) kmax = Sr;
    int ktiles = (kmax + BK - 1) / BK;              // extra cols are zeros in attn
    gemm_core<false,true>(dsm, attn, V, nullptr, Cc, i0, blockIdx.x*BN,
                          ktiles, Sr, rate*DM, 4*DM, 1.f);
}

__global__ __launch_bounds__(256,2) void k_final(float* __restrict__ out) {
    extern __shared__ __half dsm[];
    gemm_core<false,false>(dsm, g_comb, g_weff, g_beff, out,
                           blockIdx.y*BM, blockIdx.x*BN, (4*DM)/BK, 4*DM, DM, DM, 1.f);
}

// ---------------- masked softmax for all 4 rates + avg attention ----------------
__global__ __launch_bounds__(256) void softmax_kernel(float* __restrict__ avg_out)
{
    __shared__ float srow[SQ];
    __shared__ float avgs[SQ];
    __shared__ float wred[8];

    int i = blockIdx.x;
    int b = blockIdx.y;
    int tid = threadIdx.x;
    int lane = tid & 31;
    int warp = tid >> 5;

    const float* sc = &g_scores[((long)b*SQ + i) * SQ];
    for (int j = tid; j <= i; j += 256) srow[j] = sc[j];
    for (int j = tid; j < SQ; j += 256) avgs[j] = 0.f;
    __syncthreads();

    #pragma unroll
    for (int rr = 0; rr < 4; rr++) {
        const int rate = 1 << rr;
        const int Sr = SQ >> rr;
        __half* attn;
        if (rr == 0)      attn = g_attn1;
        else if (rr == 1) attn = g_attn2;
        else if (rr == 2) attn = g_attn4;
        else              attn = g_attn8;

        int count = i / rate + 1;

        // ---- max (warp shuffle + 8-entry combine) ----
        float mx = -1e30f;
        for (int m = tid; m < count; m += 256) mx = fmaxf(mx, srow[m*rate]);
        #pragma unroll
        for (int o = 16; o >= 1; o >>= 1) mx = fmaxf(mx, __shfl_xor_sync(0xffffffffu, mx, o));
        if (lane == 0) wred[warp] = mx;
        __syncthreads();
        mx = wred[0];
        #pragma unroll
        for (int w = 1; w < 8; w++) mx = fmaxf(mx, wred[w]);
        __syncthreads();   // wred free for reuse

        // ---- sum ----
        float sum = 0.f;
        for (int m = tid; m < count; m += 256) sum += __expf(srow[m*rate] - mx);
        #pragma unroll
        for (int o = 16; o >= 1; o >>= 1) sum += __shfl_xor_sync(0xffffffffu, sum, o);
        if (lane == 0) wred[warp] = sum;
        __syncthreads();
        sum = wred[0];
        #pragma unroll
        for (int w = 1; w < 8; w++) sum += wred[w];
        float inv = 1.0f / sum;

        // ---- write compacted attn + accumulate avg ----
        __half* arow = attn + ((long)b*SQ + i) * Sr;
        for (int m = tid; m < Sr; m += 256) {
            float v = 0.f;
            if (m < count) {
                v = __expf(srow[m*rate] - mx) * inv;
                avgs[m*rate] += 0.25f * v;   // unique (rate, j) writer within this rate
            }
            arow[m] = __float2half_rn(v);
        }
        __syncthreads();   // protects wred + avgs across rates
    }

    float* out = avg_out + ((long)b*SQ + i) * SQ;
    for (int j = tid; j < SQ; j += 256) out[j] = (j <= i) ? avgs[j] : 0.f;
}

// ---------------- launch ----------------
extern "C" void kernel_launch(void* const* d_in, const int* in_sizes, int n_in,
                              void* d_out, int out_size) {
    const float* x  = (const float*)d_in[0];
    const float* Wq = (const float*)d_in[1];
    const float* bq = (const float*)d_in[2];
    const float* Wk = (const float*)d_in[3];
    const float* bk = (const float*)d_in[4];
    const float* Wv = (const float*)d_in[5];
    const float* bv = (const float*)d_in[6];
    const float* Wr = (const float*)d_in[7];
    const float* br = (const float*)d_in[8];
    const float* Wo = (const float*)d_in[9];
    const float* bo = (const float*)d_in[10];
    float* out = (float*)d_out;

    __half *xh, *wqh, *wkh, *wvh, *wrh, *woh;
    cudaGetSymbolAddress((void**)&xh,  g_xh);
    cudaGetSymbolAddress((void**)&wqh, g_wqh);
    cudaGetSymbolAddress((void**)&wkh, g_wkh);
    cudaGetSymbolAddress((void**)&wvh, g_wvh);
    cudaGetSymbolAddress((void**)&wrh, g_wrh);
    cudaGetSymbolAddress((void**)&woh, g_woh);

    // opt-in dynamic smem (idempotent; host-side, not a stream op)
    cudaFuncSetAttribute(k_weff,  cudaFuncAttributeMaxDynamicSharedMemorySize, DSMEM);
    cudaFuncSetAttribute(k_qkv_b, cudaFuncAttributeMaxDynamicSharedMemorySize, DSMEM);
    cudaFuncSetAttribute(k_scores,cudaFuncAttributeMaxDynamicSharedMemorySize, DSMEM);
    cudaFuncSetAttribute(k_attnv, cudaFuncAttributeMaxDynamicSharedMemorySize, DSMEM);
    cudaFuncSetAttribute(k_final, cudaFuncAttributeMaxDynamicSharedMemorySize, DSMEM);

    dim3 blk(256);

    // convert GEMM inputs to fp16
    k_tohalf<<<(MS*DM/4 + 255)/256, blk>>>(x,  xh,  MS*DM/4);
    k_tohalf<<<(DM*DM/4 + 255)/256, blk>>>(Wq, wqh, DM*DM/4);
    k_tohalf<<<(DM*DM/4 + 255)/256, blk>>>(Wk, wkh, DM*DM/4);
    k_tohalf<<<(DM*DM/4 + 255)/256, blk>>>(Wv, wvh, DM*DM/4);
    k_tohalf<<<(4*DM*DM/4 + 255)/256, blk>>>(Wr, wrh, 4*DM*DM/4);
    k_tohalf<<<(4*DM*DM/4 + 255)/256, blk>>>(Wo, woh, 4*DM*DM/4);

    // fused output weights: Weff[r] = Wr[r] @ Wo_r ; beff = br_flat @ Wo + bo
    k_weff<<<dim3(DM/BN, DM/BM, 4), blk, DSMEM>>>();
    k_beff<<<dim3(2), blk>>>(br, Wo, bo);

    // QKV projections
    k_qkv_b<<<dim3(DM/BN, MS/BM, 3), blk, DSMEM>>>(bq, bk, bv);

    // scores = Q @ K^T / sqrt(D), lower-triangle tiles only
    k_scores<<<dim3(SQ/BN, SQ/BM, NB), blk, DSMEM>>>();

    // masked softmax for all rates + avg attention
    softmax_kernel<<<dim3(SQ, NB), blk>>>(out + (long)MS*DM);

    // ctx[r] = attn_c[r] @ V(dilated rows) -> concat buffer
    k_attnv<<<dim3(DM/BN, SQ/BM, 4*NB), blk, DSMEM>>>();

    // output = ctxcat @ Weff + beff
    k_final<<<dim3(DM/BN, MS/BM, 1), blk, DSMEM>>>(out);
}

// round 6
// speedup vs baseline: 7.5199x; 1.5997x over previous
#include <cuda_runtime.h>
#include <cuda_fp16.h>
#include <cstdint>

#define SQ 2048
#define DM 512
#define NB 2
#define MS (NB*SQ)   // 4096

#define BM 128
#define BN 128
#define BK 32
#define APITCH 40     // halves; [row][k] layout (A, NT-B)
#define BPITCH 136    // halves; [k][n] layout (NN-B)
#define ASTG (BM*APITCH)          // 5120 halves per stage
#define BSTG 5120                 // max(32*136=4352, 128*40=5120)
#define NSTAGE 3
#define DSMEM (NSTAGE*(ASTG+BSTG)*2)   // 61440 bytes

// ---------------- scratch (static device globals; no allocation) ----------------
__device__ __half g_xh[MS*DM];
__device__ __half g_wqh[DM*DM];
__device__ __half g_wkh[DM*DM];
__device__ __half g_wvh[DM*DM];
__device__ __half g_wrh[4*DM*DM];
__device__ __half g_woh[4*DM*DM];
__device__ __half g_weff[4*DM*DM];   // [2048 x 512]
__device__ float  g_beff[DM];
__device__ __half g_Q[MS*DM];
__device__ __half g_K[MS*DM];
__device__ __half g_V[MS*DM];
__device__ float  g_scores[(long)NB*SQ*SQ];   // reused as split-K partials for k_final
__device__ __half g_attn1[(long)NB*SQ*SQ];
__device__ __half g_attn2[(long)NB*SQ*(SQ/2)];
__device__ __half g_attn4[(long)NB*SQ*(SQ/4)];
__device__ __half g_attn8[(long)NB*SQ*(SQ/8)];
__device__ __half g_comb[(long)MS*4*DM];  // ctx concat [4096 x 2048]

// ---------------- PTX helpers ----------------
__device__ __forceinline__ void mma16(float* c, const uint32_t* a, const uint32_t* b) {
    asm volatile(
        "mma.sync.aligned.m16n8k16.row.col.f32.f16.f16.f32 "
        "{%0,%1,%2,%3}, {%4,%5,%6,%7}, {%8,%9}, {%0,%1,%2,%3};"
        : "+f"(c[0]), "+f"(c[1]), "+f"(c[2]), "+f"(c[3])
        : "r"(a[0]), "r"(a[1]), "r"(a[2]), "r"(a[3]), "r"(b[0]), "r"(b[1]));
}
__device__ __forceinline__ void ldsm4(uint32_t* r, uint32_t addr) {
    asm volatile("ldmatrix.sync.aligned.m8n8.x4.shared.b16 {%0,%1,%2,%3}, [%4];"
                 : "=r"(r[0]), "=r"(r[1]), "=r"(r[2]), "=r"(r[3]) : "r"(addr));
}
__device__ __forceinline__ void ldsm4t(uint32_t* r, uint32_t addr) {
    asm volatile("ldmatrix.sync.aligned.m8n8.x4.trans.shared.b16 {%0,%1,%2,%3}, [%4];"
                 : "=r"(r[0]), "=r"(r[1]), "=r"(r[2]), "=r"(r[3]) : "r"(addr));
}
__device__ __forceinline__ void cpa16(uint32_t saddr, const void* g) {
    asm volatile("cp.async.cg.shared.global [%0], [%1], 16;" :: "r"(saddr), "l"(g));
}
__device__ __forceinline__ void cp_commit() { asm volatile("cp.async.commit_group;"); }
__device__ __forceinline__ void cp_wait1()  { asm volatile("cp.async.wait_group 1;"); }

// ---------------- 128x128x(32*ktiles) fp16 MMA core, 3-stage pipeline ----------------
template<bool NT, bool HOUT>
__device__ __forceinline__ void gemm_core(
    __half* dsm,
    const __half* __restrict__ A, const __half* __restrict__ B,
    const float* __restrict__ bias, void* __restrict__ Cv,
    int i0, int n0, int ktiles, int lda, int ldb, int ldc, float alpha)
{
    __half* As = dsm;
    __half* Bs = dsm + NSTAGE * ASTG;

    const int tid  = threadIdx.x;
    const int lane = tid & 31;
    const int wid  = tid >> 5;
    const int wm   = wid >> 2;        // 0..1
    const int wn   = wid & 3;         // 0..3
    const int gq   = lane >> 2;       // 0..7
    const int tg   = lane & 3;        // 0..3
    const int quad = lane >> 3;       // 0..3
    const int wthr = lane & 7;        // 0..7

    const uint32_t a_base = (uint32_t)__cvta_generic_to_shared(As);
    const uint32_t b_base = (uint32_t)__cvta_generic_to_shared(Bs);

    float acc[4][4][4];
    #pragma unroll
    for (int a = 0; a < 4; a++)
        #pragma unroll
        for (int b2 = 0; b2 < 4; b2++)
            #pragma unroll
            for (int c = 0; c < 4; c++) acc[a][b2][c] = 0.f;

    auto issue = [&](int kt, int st) {
        const int k0 = kt * BK;
        const uint32_t ab = a_base + (uint32_t)st * ASTG * 2u;
        const uint32_t bb = b_base + (uint32_t)st * BSTG * 2u;
        #pragma unroll
        for (int j = 0; j < 2; j++) {
            int e = tid + j * 256;
            int m = e >> 2, kq = (e & 3) * 8;
            cpa16(ab + (uint32_t)(m * APITCH + kq) * 2u,
                  &A[(long)(i0 + m) * lda + k0 + kq]);
            if (NT) {
                cpa16(bb + (uint32_t)(m * APITCH + kq) * 2u,
                      &B[(long)(n0 + m) * ldb + k0 + kq]);
            } else {
                int kr = e >> 4, nq = (e & 15) * 8;
                cpa16(bb + (uint32_t)(kr * BPITCH + nq) * 2u,
                      &B[(long)(k0 + kr) * ldb + n0 + nq]);
            }
        }
    };

    issue(0, 0);
    cp_commit();
    if (ktiles > 1) issue(1, 1);
    cp_commit();

    int cur = 0;
    int wst = 2;
    for (int kt = 0; kt < ktiles; kt++) {
        cp_wait1();
        __syncthreads();

        if (kt + 2 < ktiles) issue(kt + 2, wst);
        cp_commit();

        const uint32_t ab = a_base + (uint32_t)cur * ASTG * 2u;
        const uint32_t bb = b_base + (uint32_t)cur * BSTG * 2u;

        #pragma unroll
        for (int ks = 0; ks < 2; ks++) {
            uint32_t af[4][4], bf[4][2];
            #pragma unroll
            for (int mt = 0; mt < 4; mt++) {
                int arow = wm*64 + mt*16 + wthr + (quad & 1) * 8;
                int acol = ks*16 + (quad >> 1) * 8;
                ldsm4(af[mt], ab + (uint32_t)(arow * APITCH + acol) * 2u);
            }
            #pragma unroll
            for (int nh = 0; nh < 2; nh++) {
                int nc = wn*32 + nh*16;
                uint32_t r[4];
                if (NT) {
                    int brow = nc + wthr + (quad >> 1) * 8;
                    int bcol = ks*16 + (quad & 1) * 8;
                    ldsm4(r, bb + (uint32_t)(brow * APITCH + bcol) * 2u);
                } else {
                    int brow = ks*16 + wthr + (quad & 1) * 8;
                    int bcol = nc + (quad >> 1) * 8;
                    ldsm4t(r, bb + (uint32_t)(brow * BPITCH + bcol) * 2u);
                }
                bf[nh*2+0][0] = r[0]; bf[nh*2+0][1] = r[1];
                bf[nh*2+1][0] = r[2]; bf[nh*2+1][1] = r[3];
            }
            #pragma unroll
            for (int mt = 0; mt < 4; mt++)
                #pragma unroll
                for (int nt = 0; nt < 4; nt++)
                    mma16(acc[mt][nt], af[mt], bf[nt]);
        }

        cur = (cur + 1 == NSTAGE) ? 0 : cur + 1;
        wst = (wst + 1 == NSTAGE) ? 0 : wst + 1;
    }

    // ---- epilogue ----
    #pragma unroll
    for (int nt = 0; nt < 4; nt++) {
        int col = n0 + wn*32 + nt*8 + tg*2;
        float bx = 0.f, by = 0.f;
        if (bias) { bx = bias[col]; by = bias[col+1]; }
        #pragma unroll
        for (int mt = 0; mt < 4; mt++) {
            int row = i0 + wm*64 + mt*16 + gq;
            const float* c = acc[mt][nt];
            float v0 = c[0]*alpha + bx, v1 = c[1]*alpha + by;
            float v2 = c[2]*alpha + bx, v3 = c[3]*alpha + by;
            if (HOUT) {
                __half* C = (__half*)Cv;
                *(__half2*)&C[(long)row*ldc + col]     = __floats2half2_rn(v0, v1);
                *(__half2*)&C[(long)(row+8)*ldc + col] = __floats2half2_rn(v2, v3);
            } else {
                float* C = (float*)Cv;
                *(float2*)&C[(long)row*ldc + col]     = make_float2(v0, v1);
                *(float2*)&C[(long)(row+8)*ldc + col] = make_float2(v2, v3);
            }
        }
    }
}

// ---------------- fused fp32->fp16 conversion of all inputs ----------------
#define C0 524288            // x        (MS*DM/4)
#define C1 (C0+65536)        // Wq
#define C2 (C1+65536)        // Wk
#define C3 (C2+65536)        // Wv
#define C4 (C3+262144)       // Wr
#define C5 (C4+262144)       // Wo  -> total float4 count
__global__ __launch_bounds__(256) void k_convert_all(
    const float* __restrict__ x,  const float* __restrict__ Wq,
    const float* __restrict__ Wk, const float* __restrict__ Wv,
    const float* __restrict__ Wr, const float* __restrict__ Wo)
{
    int i = blockIdx.x * 256 + threadIdx.x;
    const float* s; __half* d; int off;
    if (i < C0)      { s = x;  d = g_xh;  off = i; }
    else if (i < C1) { s = Wq; d = g_wqh; off = i - C0; }
    else if (i < C2) { s = Wk; d = g_wkh; off = i - C1; }
    else if (i < C3) { s = Wv; d = g_wvh; off = i - C2; }
    else if (i < C4) { s = Wr; d = g_wrh; off = i - C3; }
    else             { s = Wo; d = g_woh; off = i - C4; }
    float4 v = ((const float4*)s)[off];
    *(__half2*)&d[off*4]   = __floats2half2_rn(v.x, v.y);
    *(__half2*)&d[off*4+2] = __floats2half2_rn(v.z, v.w);
}

// ---------------- beff = br_flat @ Wo + bo (parallel) ----------------
__global__ __launch_bounds__(256) void k_beff(const float* __restrict__ br,
                                              const float* __restrict__ Wo,
                                              const float* __restrict__ bo) {
    __shared__ float sm[8][32];
    int tx = threadIdx.x & 31, ty = threadIdx.x >> 5;
    int n = blockIdx.x * 32 + tx;
    float p = 0.f;
    for (int k = ty; k < 4*DM; k += 8) p += br[k] * Wo[(long)k*DM + n];
    sm[ty][tx] = p;
    __syncthreads();
    if (ty == 0) {
        float s = bo[n];
        #pragma unroll
        for (int w = 0; w < 8; w++) s += sm[w][tx];
        g_beff[n] = s;
    }
}

// ---------------- QKV projections + Weff (merged launch) ----------------
__global__ __launch_bounds__(256,2) void k_qkv_weff(
    const float* __restrict__ bq, const float* __restrict__ bk, const float* __restrict__ bv) {
    extern __shared__ __half dsm[];
    if (blockIdx.y < 32) {
        int z = blockIdx.z;
        const __half* W = (z == 0) ? g_wqh : (z == 1) ? g_wkh : g_wvh;
        const float* b = (z == 0) ? bq : (z == 1) ? bk : bv;
        __half* O = (z == 0) ? g_Q : (z == 1) ? g_K : g_V;
        gemm_core<false,true>(dsm, g_xh, W, b, O, blockIdx.y*BM, blockIdx.x*BN,
                              DM/BK, DM, DM, DM, 1.f);
    } else {
        int idx = (blockIdx.y - 32) * 12 + blockIdx.z * 4 + blockIdx.x;
        if (idx >= 64) return;
        int r = idx >> 4, t = idx & 15;
        gemm_core<false,true>(dsm, g_wrh + (long)r*DM*DM, g_woh + (long)r*DM*DM, nullptr,
                              g_weff + (long)r*DM*DM,
                              (t >> 2)*BM, (t & 3)*BN, DM/BK, DM, DM, DM, 1.f);
    }
}

__global__ __launch_bounds__(256,2) void k_scores() {
    extern __shared__ __half dsm[];
    int i0 = blockIdx.y * BM;
    int j0 = blockIdx.x * BN;
    if (j0 > i0 + (BM-1)) return;   // fully-masked tile, never read
    int b = blockIdx.z;
    gemm_core<true,false>(dsm, g_Q + (long)b*SQ*DM, g_K + (long)b*SQ*DM, nullptr,
                          g_scores + (long)b*SQ*SQ, i0, j0,
                          DM/BK, DM, DM, SQ, 0.044194173824159216f);
}

__global__ __launch_bounds__(256,2) void k_attnv() {
    extern __shared__ __half dsm[];
    int z = blockIdx.z;
    int r = z >> 1, b = z & 1;      // heavy rates first (z-major block order)
    int rate = 1 << r, Sr = SQ >> r;
    const __half* attn = ((r==0) ? g_attn1 : (r==1) ? g_attn2 : (r==2) ? g_attn4 : g_attn8)
                        + (long)b*SQ*Sr;
    const __half* V = g_V + (long)b*SQ*DM;
    __half* Cc = g_comb + (long)b*SQ*4*DM + r*DM;   // concat layout [4096 x 2048]
    int i0 = blockIdx.y * BM;
    int kmax = (i0 + BM - 1)/rate + 1;
    if (kmax > Sr) kmax = Sr;
    int ktiles = (kmax + BK - 1) / BK;
    gemm_core<false,true>(dsm, attn, V, nullptr, Cc, i0, blockIdx.x*BN,
                          ktiles, Sr, rate*DM, 4*DM, 1.f);
}

// split-K final GEMM: partials into g_scores (dead after softmax)
__global__ __launch_bounds__(256,2) void k_final_split() {
    extern __shared__ __half dsm[];
    int z = blockIdx.z;
    float* pbuf = g_scores + (long)z * MS * DM;
    gemm_core<false,false>(dsm, g_comb + z*1024, g_weff + (long)z*1024*DM, nullptr, pbuf,
                           blockIdx.y*BM, blockIdx.x*BN, 1024/BK, 4*DM, DM, DM, 1.f);
}

__global__ __launch_bounds__(256) void k_addout(float* __restrict__ out) {
    int i = blockIdx.x * 256 + threadIdx.x;      // float4 index, 524288 total
    const float4* p0 = (const float4*)g_scores;
    const float4* p1 = (const float4*)(g_scores + (long)MS*DM);
    float4 a = p0[i], b = p1[i];
    float4 bb = ((const float4*)g_beff)[i & 127];   // row length 512 = 128 float4
    float4 o;
    o.x = a.x + b.x + bb.x; o.y = a.y + b.y + bb.y;
    o.z = a.z + b.z + bb.z; o.w = a.w + b.w + bb.w;
    ((float4*)out)[i] = o;
}

// ---------------- masked softmax for all 4 rates + avg attention ----------------
__global__ __launch_bounds__(256) void softmax_kernel(float* __restrict__ avg_out)
{
    __shared__ float srow[SQ];
    __shared__ float avgs[SQ];
    __shared__ float evals[SQ];
    __shared__ float wred[8];

    int i = blockIdx.x;
    int b = blockIdx.y;
    int tid = threadIdx.x;
    int lane = tid & 31;
    int warp = tid >> 5;

    const float* sc = &g_scores[((long)b*SQ + i) * SQ];
    for (int j = tid; j <= i; j += 256) srow[j] = sc[j];
    for (int j = tid; j < SQ; j += 256) avgs[j] = 0.f;
    __syncthreads();

    #pragma unroll
    for (int rr = 0; rr < 4; rr++) {
        const int rate = 1 << rr;
        const int Sr = SQ >> rr;
        __half* attn;
        if (rr == 0)      attn = g_attn1;
        else if (rr == 1) attn = g_attn2;
        else if (rr == 2) attn = g_attn4;
        else              attn = g_attn8;

        int count = i / rate + 1;

        // ---- max ----
        float mx = -1e30f;
        for (int m = tid; m < count; m += 256) mx = fmaxf(mx, srow[m*rate]);
        #pragma unroll
        for (int o = 16; o >= 1; o >>= 1) mx = fmaxf(mx, __shfl_xor_sync(0xffffffffu, mx, o));
        if (lane == 0) wred[warp] = mx;
        __syncthreads();
        mx = wred[0];
        #pragma unroll
        for (int w = 1; w < 8; w++) mx = fmaxf(mx, wred[w]);
        __syncthreads();

        // ---- sum (cache exp values; same-thread reuse below) ----
        float sum = 0.f;
        for (int m = tid; m < count; m += 256) {
            float e = __expf(srow[m*rate] - mx);
            evals[m] = e;
            sum += e;
        }
        #pragma unroll
        for (int o = 16; o >= 1; o >>= 1) sum += __shfl_xor_sync(0xffffffffu, sum, o);
        if (lane == 0) wred[warp] = sum;
        __syncthreads();
        sum = wred[0];
        #pragma unroll
        for (int w = 1; w < 8; w++) sum += wred[w];
        float inv = 1.0f / sum;

        // ---- write compacted attn + accumulate avg ----
        __half* arow = attn + ((long)b*SQ + i) * Sr;
        for (int m = tid; m < Sr; m += 256) {
            float v = 0.f;
            if (m < count) {
                v = evals[m] * inv;
                avgs[m*rate] += 0.25f * v;
            }
            arow[m] = __float2half_rn(v);
        }
        __syncthreads();
    }

    float* out = avg_out + ((long)b*SQ + i) * SQ;
    for (int j = tid; j < SQ; j += 256) out[j] = (j <= i) ? avgs[j] : 0.f;
}

// ---------------- launch ----------------
extern "C" void kernel_launch(void* const* d_in, const int* in_sizes, int n_in,
                              void* d_out, int out_size) {
    const float* x  = (const float*)d_in[0];
    const float* Wq = (const float*)d_in[1];
    const float* bq = (const float*)d_in[2];
    const float* Wk = (const float*)d_in[3];
    const float* bk = (const float*)d_in[4];
    const float* Wv = (const float*)d_in[5];
    const float* bv = (const float*)d_in[6];
    const float* Wr = (const float*)d_in[7];
    const float* br = (const float*)d_in[8];
    const float* Wo = (const float*)d_in[9];
    const float* bo = (const float*)d_in[10];
    float* out = (float*)d_out;

    cudaFuncSetAttribute(k_qkv_weff,   cudaFuncAttributeMaxDynamicSharedMemorySize, DSMEM);
    cudaFuncSetAttribute(k_scores,     cudaFuncAttributeMaxDynamicSharedMemorySize, DSMEM);
    cudaFuncSetAttribute(k_attnv,      cudaFuncAttributeMaxDynamicSharedMemorySize, DSMEM);
    cudaFuncSetAttribute(k_final_split,cudaFuncAttributeMaxDynamicSharedMemorySize, DSMEM);

    dim3 blk(256);

    // all fp32->fp16 conversions in one launch
    k_convert_all<<<C5/256, blk>>>(x, Wq, Wk, Wv, Wr, Wo);

    // beff = br_flat @ Wo + bo
    k_beff<<<dim3(16), blk>>>(br, Wo, bo);

    // QKV projections + Weff[r] = Wr[r] @ Wo_r, one launch
    k_qkv_weff<<<dim3(DM/BN, 38, 3), blk, DSMEM>>>(bq, bk, bv);

    // scores = Q @ K^T / sqrt(D), lower-triangle tiles only
    k_scores<<<dim3(SQ/BN, SQ/BM, NB), blk, DSMEM>>>();

    // masked softmax for all rates + avg attention
    softmax_kernel<<<dim3(SQ, NB), blk>>>(out + (long)MS*DM);

    // ctx[r] = attn_c[r] @ V(dilated rows) -> concat buffer
    k_attnv<<<dim3(DM/BN, SQ/BM, 4*NB), blk, DSMEM>>>();

    // output = ctxcat @ Weff (+ beff), split-K into g_scores then reduce
    k_final_split<<<dim3(DM/BN, MS/BM, 2), blk, DSMEM>>>();
    k_addout<<<dim3(MS*DM/4/256), blk>>>(out);
}

// round 8
// speedup vs baseline: 7.6145x; 1.0126x over previous
#include <cuda_runtime.h>
#include <cuda_fp16.h>
#include <cstdint>
#include <math.h>

#define SQ 2048
#define DM 512
#define NB 2
#define MS (NB*SQ)   // 4096

#define BM 128
#define BN 128
#define BK 32
#define APITCH 40     // halves; [row][k] layout (A, NT-B)
#define BPITCH 136    // halves; [k][n] layout (NN-B)
#define ASTG (BM*APITCH)          // 5120 halves per stage
#define BSTG 5120                 // max(32*136=4352, 128*40=5120)
#define NSTAGE 4
#define DSMEM (NSTAGE*(ASTG+BSTG)*2)   // 81920 bytes

// ---------------- scratch (static device globals; no allocation) ----------------
__device__ __half g_xh[MS*DM];
__device__ __half g_wqh[DM*DM];
__device__ __half g_wkh[DM*DM];
__device__ __half g_wvh[DM*DM];
__device__ __half g_wrh[4*DM*DM];
__device__ __half g_woh[4*DM*DM];
__device__ __half g_weff[4*DM*DM];   // [2048 x 512]
__device__ float  g_beff[DM];
__device__ __half g_Q[MS*DM];
__device__ __half g_K[MS*DM];
__device__ __half g_V[MS*DM];
__device__ float  g_scores[(long)NB*SQ*SQ];   // reused as split-K partials for k_final
__device__ __half g_attn1[(long)NB*SQ*SQ];
__device__ __half g_attn2[(long)NB*SQ*(SQ/2)];
__device__ __half g_attn4[(long)NB*SQ*(SQ/4)];
__device__ __half g_attn8[(long)NB*SQ*(SQ/8)];
__device__ __half g_comb[(long)MS*4*DM];  // ctx concat [4096 x 2048]

// ---------------- PTX helpers ----------------
__device__ __forceinline__ void mma16(float* c, const uint32_t* a, const uint32_t* b) {
    asm volatile(
        "mma.sync.aligned.m16n8k16.row.col.f32.f16.f16.f32 "
        "{%0,%1,%2,%3}, {%4,%5,%6,%7}, {%8,%9}, {%0,%1,%2,%3};"
        : "+f"(c[0]), "+f"(c[1]), "+f"(c[2]), "+f"(c[3])
        : "r"(a[0]), "r"(a[1]), "r"(a[2]), "r"(a[3]), "r"(b[0]), "r"(b[1]));
}
__device__ __forceinline__ void ldsm4(uint32_t* r, uint32_t addr) {
    asm volatile("ldmatrix.sync.aligned.m8n8.x4.shared.b16 {%0,%1,%2,%3}, [%4];"
                 : "=r"(r[0]), "=r"(r[1]), "=r"(r[2]), "=r"(r[3]) : "r"(addr));
}
__device__ __forceinline__ void ldsm4t(uint32_t* r, uint32_t addr) {
    asm volatile("ldmatrix.sync.aligned.m8n8.x4.trans.shared.b16 {%0,%1,%2,%3}, [%4];"
                 : "=r"(r[0]), "=r"(r[1]), "=r"(r[2]), "=r"(r[3]) : "r"(addr));
}
__device__ __forceinline__ void cpa16(uint32_t saddr, const void* g) {
    asm volatile("cp.async.cg.shared.global [%0], [%1], 16;" :: "r"(saddr), "l"(g));
}
__device__ __forceinline__ void cp_commit() { asm volatile("cp.async.commit_group;"); }
__device__ __forceinline__ void cp_wait2()  { asm volatile("cp.async.wait_group 2;" ::: "memory"); }

// ---------------- 128x128x(32*ktiles) fp16 MMA core, 4-stage pipeline ----------------
template<bool NT, bool HOUT>
__device__ __forceinline__ void gemm_core(
    __half* dsm,
    const __half* __restrict__ A, const __half* __restrict__ B,
    const float* __restrict__ bias, void* __restrict__ Cv,
    int i0, int n0, int ktiles, int lda, int ldb, int ldc, float alpha)
{
    __half* As = dsm;
    __half* Bs = dsm + NSTAGE * ASTG;

    const int tid  = threadIdx.x;
    const int lane = tid & 31;
    const int wid  = tid >> 5;
    const int wm   = wid >> 2;        // 0..1
    const int wn   = wid & 3;         // 0..3
    const int gq   = lane >> 2;       // 0..7
    const int tg   = lane & 3;        // 0..3
    const int quad = lane >> 3;       // 0..3
    const int wthr = lane & 7;        // 0..7

    const uint32_t a_base = (uint32_t)__cvta_generic_to_shared(As);
    const uint32_t b_base = (uint32_t)__cvta_generic_to_shared(Bs);

    float acc[4][4][4];
    #pragma unroll
    for (int a = 0; a < 4; a++)
        #pragma unroll
        for (int b2 = 0; b2 < 4; b2++)
            #pragma unroll
            for (int c = 0; c < 4; c++) acc[a][b2][c] = 0.f;

    auto issue = [&](int kt, int st) {
        const int k0 = kt * BK;
        const uint32_t ab = a_base + (uint32_t)st * ASTG * 2u;
        const uint32_t bb = b_base + (uint32_t)st * BSTG * 2u;
        #pragma unroll
        for (int j = 0; j < 2; j++) {
            int e = tid + j * 256;
            int m = e >> 2, kq = (e & 3) * 8;
            cpa16(ab + (uint32_t)(m * APITCH + kq) * 2u,
                  &A[(long)(i0 + m) * lda + k0 + kq]);
            if (NT) {
                cpa16(bb + (uint32_t)(m * APITCH + kq) * 2u,
                      &B[(long)(n0 + m) * ldb + k0 + kq]);
            } else {
                int kr = e >> 4, nq = (e & 15) * 8;
                cpa16(bb + (uint32_t)(kr * BPITCH + nq) * 2u,
                      &B[(long)(k0 + kr) * ldb + n0 + nq]);
            }
        }
    };

    // prologue: 3 groups (some possibly empty), uniform accounting
    issue(0, 0);
    cp_commit();
    if (ktiles > 1) issue(1, 1);
    cp_commit();
    if (ktiles > 2) issue(2, 2);
    cp_commit();

    int cur = 0;       // stage holding k-tile kt
    int wst = 3;       // stage to write k-tile kt+3
    for (int kt = 0; kt < ktiles; kt++) {
        cp_wait2();            // group for tile kt complete (<=2 newer pending)
        __syncthreads();       // all warps done with stage wst's previous contents

        if (kt + 3 < ktiles) issue(kt + 3, wst);
        cp_commit();           // one commit per iteration, possibly empty

        const uint32_t ab = a_base + (uint32_t)cur * ASTG * 2u;
        const uint32_t bb = b_base + (uint32_t)cur * BSTG * 2u;

        #pragma unroll
        for (int ks = 0; ks < 2; ks++) {
            uint32_t af[4][4], bf[4][2];
            #pragma unroll
            for (int mt = 0; mt < 4; mt++) {
                int arow = wm*64 + mt*16 + wthr + (quad & 1) * 8;
                int acol = ks*16 + (quad >> 1) * 8;
                ldsm4(af[mt], ab + (uint32_t)(arow * APITCH + acol) * 2u);
            }
            #pragma unroll
            for (int nh = 0; nh < 2; nh++) {
                int nc = wn*32 + nh*16;
                uint32_t r[4];
                if (NT) {
                    int brow = nc + wthr + (quad >> 1) * 8;
                    int bcol = ks*16 + (quad & 1) * 8;
                    ldsm4(r, bb + (uint32_t)(brow * APITCH + bcol) * 2u);
                } else {
                    int brow = ks*16 + wthr + (quad & 1) * 8;
                    int bcol = nc + (quad >> 1) * 8;
                    ldsm4t(r, bb + (uint32_t)(brow * BPITCH + bcol) * 2u);
                }
                bf[nh*2+0][0] = r[0]; bf[nh*2+0][1] = r[1];
                bf[nh*2+1][0] = r[2]; bf[nh*2+1][1] = r[3];
            }
            #pragma unroll
            for (int mt = 0; mt < 4; mt++)
                #pragma unroll
                for (int nt = 0; nt < 4; nt++)
                    mma16(acc[mt][nt], af[mt], bf[nt]);
        }

        cur = (cur + 1 == NSTAGE) ? 0 : cur + 1;
        wst = (wst + 1 == NSTAGE) ? 0 : wst + 1;
    }

    // ---- epilogue ----
    #pragma unroll
    for (int nt = 0; nt < 4; nt++) {
        int col = n0 + wn*32 + nt*8 + tg*2;
        float bx = 0.f, by = 0.f;
        if (bias) { bx = bias[col]; by = bias[col+1]; }
        #pragma unroll
        for (int mt = 0; mt < 4; mt++) {
            int row = i0 + wm*64 + mt*16 + gq;
            const float* c = acc[mt][nt];
            float v0 = c[0]*alpha + bx, v1 = c[1]*alpha + by;
            float v2 = c[2]*alpha + bx, v3 = c[3]*alpha + by;
            if (HOUT) {
                __half* C = (__half*)Cv;
                *(__half2*)&C[(long)row*ldc + col]     = __floats2half2_rn(v0, v1);
                *(__half2*)&C[(long)(row+8)*ldc + col] = __floats2half2_rn(v2, v3);
            } else {
                float* C = (float*)Cv;
                *(float2*)&C[(long)row*ldc + col]     = make_float2(v0, v1);
                *(float2*)&C[(long)(row+8)*ldc + col] = make_float2(v2, v3);
            }
        }
    }
}

// ---------------- fused fp32->fp16 conversion of all inputs ----------------
#define C0 524288            // x        (MS*DM/4)
#define C1 (C0+65536)        // Wq
#define C2 (C1+65536)        // Wk
#define C3 (C2+65536)        // Wv
#define C4 (C3+262144)       // Wr
#define C5 (C4+262144)       // Wo  -> total float4 count
__global__ __launch_bounds__(256) void k_convert_all(
    const float* __restrict__ x,  const float* __restrict__ Wq,
    const float* __restrict__ Wk, const float* __restrict__ Wv,
    const float* __restrict__ Wr, const float* __restrict__ Wo)
{
    int i = blockIdx.x * 256 + threadIdx.x;
    const float* s; __half* d; int off;
    if (i < C0)      { s = x;  d = g_xh;  off = i; }
    else if (i < C1) { s = Wq; d = g_wqh; off = i - C0; }
    else if (i < C2) { s = Wk; d = g_wkh; off = i - C1; }
    else if (i < C3) { s = Wv; d = g_wvh; off = i - C2; }
    else if (i < C4) { s = Wr; d = g_wrh; off = i - C3; }
    else             { s = Wo; d = g_woh; off = i - C4; }
    float4 v = ((const float4*)s)[off];
    *(__half2*)&d[off*4]   = __floats2half2_rn(v.x, v.y);
    *(__half2*)&d[off*4+2] = __floats2half2_rn(v.z, v.w);
}

// ---------------- beff = br_flat @ Wo + bo (parallel) ----------------
__global__ __launch_bounds__(256) void k_beff(const float* __restrict__ br,
                                              const float* __restrict__ Wo,
                                              const float* __restrict__ bo) {
    __shared__ float sm[8][32];
    int tx = threadIdx.x & 31, ty = threadIdx.x >> 5;
    int n = blockIdx.x * 32 + tx;
    float p = 0.f;
    for (int k = ty; k < 4*DM; k += 8) p += br[k] * Wo[(long)k*DM + n];
    sm[ty][tx] = p;
    __syncthreads();
    if (ty == 0) {
        float s = bo[n];
        #pragma unroll
        for (int w = 0; w < 8; w++) s += sm[w][tx];
        g_beff[n] = s;
    }
}

// ---------------- QKV projections + Weff (merged launch) ----------------
__global__ __launch_bounds__(256,2) void k_qkv_weff(
    const float* __restrict__ bq, const float* __restrict__ bk, const float* __restrict__ bv) {
    extern __shared__ __half dsm[];
    if (blockIdx.y < 32) {
        int z = blockIdx.z;
        const __half* W = (z == 0) ? g_wqh : (z == 1) ? g_wkh : g_wvh;
        const float* b = (z == 0) ? bq : (z == 1) ? bk : bv;
        __half* O = (z == 0) ? g_Q : (z == 1) ? g_K : g_V;
        gemm_core<false,true>(dsm, g_xh, W, b, O, blockIdx.y*BM, blockIdx.x*BN,
                              DM/BK, DM, DM, DM, 1.f);
    } else {
        int idx = (blockIdx.y - 32) * 12 + blockIdx.z * 4 + blockIdx.x;
        if (idx >= 64) return;
        int r = idx >> 4, t = idx & 15;
        gemm_core<false,true>(dsm, g_wrh + (long)r*DM*DM, g_woh + (long)r*DM*DM, nullptr,
                              g_weff + (long)r*DM*DM,
                              (t >> 2)*BM, (t & 3)*BN, DM/BK, DM, DM, DM, 1.f);
    }
}

// compact lower-triangle grid: 136 tiles per batch
__global__ __launch_bounds__(256,2) void k_scores() {
    extern __shared__ __half dsm[];
    int t = blockIdx.x;
    int i = (int)((sqrtf(8.f*t + 1.f) - 1.f) * 0.5f);
    while ((i+1)*(i+2)/2 <= t) ++i;
    while (i*(i+1)/2 > t) --i;
    int j = t - i*(i+1)/2;
    int b = blockIdx.z;
    gemm_core<true,false>(dsm, g_Q + (long)b*SQ*DM, g_K + (long)b*SQ*DM, nullptr,
                          g_scores + (long)b*SQ*SQ, i*BM, j*BN,
                          DM/BK, DM, DM, SQ, 0.044194173824159216f);
}

__global__ __launch_bounds__(256,2) void k_attnv() {
    extern __shared__ __half dsm[];
    int z = blockIdx.z;
    int r = z >> 1, b = z & 1;      // heavy rates first
    int rate = 1 << r, Sr = SQ >> r;
    const __half* attn = ((r==0) ? g_attn1 : (r==1) ? g_attn2 : (r==2) ? g_attn4 : g_attn8)
                        + (long)b*SQ*Sr;
    const __half* V = g_V + (long)b*SQ*DM;
    __half* Cc = g_comb + (long)b*SQ*4*DM + r*DM;   // concat layout [4096 x 2048]
    int i0 = blockIdx.y * BM;
    int kmax = (i0 + BM - 1)/rate + 1;
    if (kmax > Sr) kmax = Sr;
    int ktiles = (kmax + BK - 1) / BK;
    gemm_core<false,true>(dsm, attn, V, nullptr, Cc, i0, blockIdx.x*BN,
                          ktiles, Sr, rate*DM, 4*DM, 1.f);
}

// split-K final GEMM: partials into g_scores (dead after softmax)
__global__ __launch_bounds__(256,2) void k_final_split() {
    extern __shared__ __half dsm[];
    int z = blockIdx.z;
    float* pbuf = g_scores + (long)z * MS * DM;
    gemm_core<false,false>(dsm, g_comb + z*1024, g_weff + (long)z*1024*DM, nullptr, pbuf,
                           blockIdx.y*BM, blockIdx.x*BN, 1024/BK, 4*DM, DM, DM, 1.f);
}

__global__ __launch_bounds__(256) void k_addout(float* __restrict__ out) {
    int i = blockIdx.x * 256 + threadIdx.x;      // float4 index, 524288 total
    const float4* p0 = (const float4*)g_scores;
    const float4* p1 = (const float4*)(g_scores + (long)MS*DM);
    float4 a = p0[i], b = p1[i];
    float4 bb = ((const float4*)g_beff)[i & 127];
    float4 o;
    o.x = a.x + b.x + bb.x; o.y = a.y + b.y + bb.y;
    o.z = a.z + b.z + bb.z; o.w = a.w + b.w + bb.w;
    ((float4*)out)[i] = o;
}

// ---------------- masked softmax for all 4 rates + avg attention ----------------
__global__ __launch_bounds__(256) void softmax_kernel(float* __restrict__ avg_out)
{
    __shared__ float srow[SQ];
    __shared__ float avgs[SQ];
    __shared__ float evals[SQ];
    __shared__ float wred[8];

    int i = blockIdx.x;
    int b = blockIdx.y;
    int tid = threadIdx.x;
    int lane = tid & 31;
    int warp = tid >> 5;

    const float* sc = &g_scores[((long)b*SQ + i) * SQ];
    for (int j = tid; j <= i; j += 256) srow[j] = sc[j];
    for (int j = tid; j < SQ; j += 256) avgs[j] = 0.f;
    __syncthreads();

    #pragma unroll
    for (int rr = 0; rr < 4; rr++) {
        const int rate = 1 << rr;
        const int Sr = SQ >> rr;
        __half* attn;
        if (rr == 0)      attn = g_attn1;
        else if (rr == 1) attn = g_attn2;
        else if (rr == 2) attn = g_attn4;
        else              attn = g_attn8;

        int count = i / rate + 1;
        // fill only what k_attnv's block-level causal bound actually reads (64-rounded)
        int mfill = (((i | (BM-1)) / rate + 1) + 63) & ~63;
        if (mfill > Sr) mfill = Sr;

        // ---- max ----
        float mx = -1e30f;
        for (int m = tid; m < count; m += 256) mx = fmaxf(mx, srow[m*rate]);
        #pragma unroll
        for (int o = 16; o >= 1; o >>= 1) mx = fmaxf(mx, __shfl_xor_sync(0xffffffffu, mx, o));
        if (lane == 0) wred[warp] = mx;
        __syncthreads();
        mx = wred[0];
        #pragma unroll
        for (int w = 1; w < 8; w++) mx = fmaxf(mx, wred[w]);
        __syncthreads();

        // ---- sum (cache exp values) ----
        float sum = 0.f;
        for (int m = tid; m < count; m += 256) {
            float e = __expf(srow[m*rate] - mx);
            evals[m] = e;
            sum += e;
        }
        #pragma unroll
        for (int o = 16; o >= 1; o >>= 1) sum += __shfl_xor_sync(0xffffffffu, sum, o);
        if (lane == 0) wred[warp] = sum;
        __syncthreads();
        sum = wred[0];
        #pragma unroll
        for (int w = 1; w < 8; w++) sum += wred[w];
        float inv = 1.0f / sum;

        // ---- write compacted attn + accumulate avg ----
        __half* arow = attn + ((long)b*SQ + i) * Sr;
        for (int m = tid; m < mfill; m += 256) {
            float v = 0.f;
            if (m < count) {
                v = evals[m] * inv;
                avgs[m*rate] += 0.25f * v;
            }
            arow[m] = __float2half_rn(v);
        }
        __syncthreads();
    }

    float* out = avg_out + ((long)b*SQ + i) * SQ;
    for (int j = tid; j < SQ; j += 256) out[j] = (j <= i) ? avgs[j] : 0.f;
}

// ---------------- launch ----------------
extern "C" void kernel_launch(void* const* d_in, const int* in_sizes, int n_in,
                              void* d_out, int out_size) {
    const float* x  = (const float*)d_in[0];
    const float* Wq = (const float*)d_in[1];
    const float* bq = (const float*)d_in[2];
    const float* Wk = (const float*)d_in[3];
    const float* bk = (const float*)d_in[4];
    const float* Wv = (const float*)d_in[5];
    const float* bv = (const float*)d_in[6];
    const float* Wr = (const float*)d_in[7];
    const float* br = (const float*)d_in[8];
    const float* Wo = (const float*)d_in[9];
    const float* bo = (const float*)d_in[10];
    float* out = (float*)d_out;

    cudaFuncSetAttribute(k_qkv_weff,   cudaFuncAttributeMaxDynamicSharedMemorySize, DSMEM);
    cudaFuncSetAttribute(k_scores,     cudaFuncAttributeMaxDynamicSharedMemorySize, DSMEM);
    cudaFuncSetAttribute(k_attnv,      cudaFuncAttributeMaxDynamicSharedMemorySize, DSMEM);
    cudaFuncSetAttribute(k_final_split,cudaFuncAttributeMaxDynamicSharedMemorySize, DSMEM);

    dim3 blk(256);

    // all fp32->fp16 conversions in one launch
    k_convert_all<<<C5/256, blk>>>(x, Wq, Wk, Wv, Wr, Wo);

    // beff = br_flat @ Wo + bo
    k_beff<<<dim3(16), blk>>>(br, Wo, bo);

    // QKV projections + Weff[r] = Wr[r] @ Wo_r, one launch
    k_qkv_weff<<<dim3(DM/BN, 38, 3), blk, DSMEM>>>(bq, bk, bv);

    // scores = Q @ K^T / sqrt(D), compact lower-triangle grid (136 tiles/batch)
    k_scores<<<dim3(136, 1, NB), blk, DSMEM>>>();

    // masked softmax for all rates + avg attention
    softmax_kernel<<<dim3(SQ, NB), blk>>>(out + (long)MS*DM);

    // ctx[r] = attn_c[r] @ V(dilated rows) -> concat buffer
    k_attnv<<<dim3(DM/BN, SQ/BM, 4*NB), blk, DSMEM>>>();

    // output = ctxcat @ Weff (+ beff), split-K into g_scores then reduce
    k_final_split<<<dim3(DM/BN, MS/BM, 2), blk, DSMEM>>>();
    k_addout<<<dim3(MS*DM/4/256), blk>>>(out);
}

// round 9
// speedup vs baseline: 8.3830x; 1.1009x over previous
#include <cuda_runtime.h>
#include <cuda_fp16.h>
#include <cstdint>
#include <math.h>

#define SQ 2048
#define DM 512
#define NB 2
#define MS (NB*SQ)   // 4096

#define BM 128
#define BN 128
#define BK 32
#define APITCH 40
#define BPITCH 136
#define ASTG (BM*APITCH)
#define BSTG 5120
#define NSTAGE 4
#define DSMEM (NSTAGE*(ASTG+BSTG)*2)   // 81920 bytes
#define UDB (3840*512)                 // per-batch Ud halves

// ---------------- scratch ----------------
__device__ __half g_xh[MS*DM];
__device__ __half g_wqh[DM*DM];
__device__ __half g_wkh[DM*DM];
__device__ __half g_wvh[DM*DM];
__device__ __half g_wrh[4*DM*DM];
__device__ __half g_woh[4*DM*DM];
__device__ __half g_weff[4*DM*DM];   // [2048 x 512]
__device__ float  g_beff[DM];
__device__ __half g_Q[MS*DM];
__device__ __half g_K[MS*DM];
__device__ __half g_V[MS*DM];
__device__ __half g_ud[NB*UDB];      // Ud_r = V(dilated) @ Weff_r, rows r0:0 r1:2048 r2:3072 r3:3584
__device__ float  g_scores[(long)NB*SQ*SQ];   // reused as 2 split partials [2][4096x512]
__device__ __half g_attn1[(long)NB*SQ*SQ];
__device__ __half g_attn2[(long)NB*SQ*(SQ/2)];
__device__ __half g_attn4[(long)NB*SQ*(SQ/4)];
__device__ __half g_attn8[(long)NB*SQ*(SQ/8)];

// ---------------- PTX helpers ----------------
__device__ __forceinline__ void mma16(float* c, const uint32_t* a, const uint32_t* b) {
    asm volatile(
        "mma.sync.aligned.m16n8k16.row.col.f32.f16.f16.f32 "
        "{%0,%1,%2,%3}, {%4,%5,%6,%7}, {%8,%9}, {%0,%1,%2,%3};"
        : "+f"(c[0]), "+f"(c[1]), "+f"(c[2]), "+f"(c[3])
        : "r"(a[0]), "r"(a[1]), "r"(a[2]), "r"(a[3]), "r"(b[0]), "r"(b[1]));
}
__device__ __forceinline__ void ldsm4(uint32_t* r, uint32_t addr) {
    asm volatile("ldmatrix.sync.aligned.m8n8.x4.shared.b16 {%0,%1,%2,%3}, [%4];"
                 : "=r"(r[0]), "=r"(r[1]), "=r"(r[2]), "=r"(r[3]) : "r"(addr));
}
__device__ __forceinline__ void ldsm4t(uint32_t* r, uint32_t addr) {
    asm volatile("ldmatrix.sync.aligned.m8n8.x4.trans.shared.b16 {%0,%1,%2,%3}, [%4];"
                 : "=r"(r[0]), "=r"(r[1]), "=r"(r[2]), "=r"(r[3]) : "r"(addr));
}
__device__ __forceinline__ void cpa16(uint32_t saddr, const void* g) {
    asm volatile("cp.async.cg.shared.global [%0], [%1], 16;" :: "r"(saddr), "l"(g));
}
__device__ __forceinline__ void cp_commit() { asm volatile("cp.async.commit_group;"); }
__device__ __forceinline__ void cp_wait2()  { asm volatile("cp.async.wait_group 2;" ::: "memory"); }

// ---------------- accumulating 128x128 MMA core (callable multiple times) ----------------
template<bool NT>
__device__ void gemm_acc(float (&acc)[4][4][4], __half* dsm,
                         const __half* __restrict__ A, const __half* __restrict__ B,
                         int i0, int n0, int ktiles, int lda, int ldb)
{
    __half* As = dsm;
    __half* Bs = dsm + NSTAGE * ASTG;

    const int tid  = threadIdx.x;
    const int lane = tid & 31;
    const int wid  = tid >> 5;
    const int wm   = wid >> 2;
    const int wn   = wid & 3;
    const int quad = lane >> 3;
    const int wthr = lane & 7;

    const uint32_t a_base = (uint32_t)__cvta_generic_to_shared(As);
    const uint32_t b_base = (uint32_t)__cvta_generic_to_shared(Bs);

    auto issue = [&](int kt, int st) {
        const int k0 = kt * BK;
        const uint32_t ab = a_base + (uint32_t)st * ASTG * 2u;
        const uint32_t bb = b_base + (uint32_t)st * BSTG * 2u;
        #pragma unroll
        for (int j = 0; j < 2; j++) {
            int e = tid + j * 256;
            int m = e >> 2, kq = (e & 3) * 8;
            cpa16(ab + (uint32_t)(m * APITCH + kq) * 2u,
                  &A[(long)(i0 + m) * lda + k0 + kq]);
            if (NT) {
                cpa16(bb + (uint32_t)(m * APITCH + kq) * 2u,
                      &B[(long)(n0 + m) * ldb + k0 + kq]);
            } else {
                int kr = e >> 4, nq = (e & 15) * 8;
                cpa16(bb + (uint32_t)(kr * BPITCH + nq) * 2u,
                      &B[(long)(k0 + kr) * ldb + n0 + nq]);
            }
        }
    };

    __syncthreads();   // previous segment's consumers done before overwriting stage 0

    issue(0, 0);
    cp_commit();
    if (ktiles > 1) issue(1, 1);
    cp_commit();
    if (ktiles > 2) issue(2, 2);
    cp_commit();

    int cur = 0, wst = 3;
    for (int kt = 0; kt < ktiles; kt++) {
        cp_wait2();
        __syncthreads();

        if (kt + 3 < ktiles) issue(kt + 3, wst);
        cp_commit();

        const uint32_t ab = a_base + (uint32_t)cur * ASTG * 2u;
        const uint32_t bb = b_base + (uint32_t)cur * BSTG * 2u;

        #pragma unroll
        for (int ks = 0; ks < 2; ks++) {
            uint32_t af[4][4], bf[4][2];
            #pragma unroll
            for (int mt = 0; mt < 4; mt++) {
                int arow = wm*64 + mt*16 + wthr + (quad & 1) * 8;
                int acol = ks*16 + (quad >> 1) * 8;
                ldsm4(af[mt], ab + (uint32_t)(arow * APITCH + acol) * 2u);
            }
            #pragma unroll
            for (int nh = 0; nh < 2; nh++) {
                int nc = wn*32 + nh*16;
                uint32_t r[4];
                if (NT) {
                    int brow = nc + wthr + (quad >> 1) * 8;
                    int bcol = ks*16 + (quad & 1) * 8;
                    ldsm4(r, bb + (uint32_t)(brow * APITCH + bcol) * 2u);
                } else {
                    int brow = ks*16 + wthr + (quad & 1) * 8;
                    int bcol = nc + (quad >> 1) * 8;
                    ldsm4t(r, bb + (uint32_t)(brow * BPITCH + bcol) * 2u);
                }
                bf[nh*2+0][0] = r[0]; bf[nh*2+0][1] = r[1];
                bf[nh*2+1][0] = r[2]; bf[nh*2+1][1] = r[3];
            }
            #pragma unroll
            for (int mt = 0; mt < 4; mt++)
                #pragma unroll
                for (int nt = 0; nt < 4; nt++)
                    mma16(acc[mt][nt], af[mt], bf[nt]);
        }

        cur = (cur + 1 == NSTAGE) ? 0 : cur + 1;
        wst = (wst + 1 == NSTAGE) ? 0 : wst + 1;
    }
}

template<bool HOUT, bool BIAS>
__device__ __forceinline__ void epi(float (&acc)[4][4][4], const float* __restrict__ bias,
                                    void* __restrict__ Cv, int i0, int n0, int ldc, float alpha)
{
    const int tid  = threadIdx.x;
    const int lane = tid & 31;
    const int wid  = tid >> 5;
    const int wm   = wid >> 2;
    const int wn   = wid & 3;
    const int gq   = lane >> 2;
    const int tg   = lane & 3;
    #pragma unroll
    for (int nt = 0; nt < 4; nt++) {
        int col = n0 + wn*32 + nt*8 + tg*2;
        float bx = 0.f, by = 0.f;
        if (BIAS) { bx = bias[col]; by = bias[col+1]; }
        #pragma unroll
        for (int mt = 0; mt < 4; mt++) {
            int row = i0 + wm*64 + mt*16 + gq;
            const float* c = acc[mt][nt];
            float v0 = c[0]*alpha + bx, v1 = c[1]*alpha + by;
            float v2 = c[2]*alpha + bx, v3 = c[3]*alpha + by;
            if (HOUT) {
                __half* C = (__half*)Cv;
                *(__half2*)&C[(long)row*ldc + col]     = __floats2half2_rn(v0, v1);
                *(__half2*)&C[(long)(row+8)*ldc + col] = __floats2half2_rn(v2, v3);
            } else {
                float* C = (float*)Cv;
                *(float2*)&C[(long)row*ldc + col]     = make_float2(v0, v1);
                *(float2*)&C[(long)(row+8)*ldc + col] = make_float2(v2, v3);
            }
        }
    }
}

#define ACC_ZERO(acc) do { \
    _Pragma("unroll") for (int a_=0;a_<4;a_++) _Pragma("unroll") for (int b_=0;b_<4;b_++) \
    _Pragma("unroll") for (int c_=0;c_<4;c_++) acc[a_][b_][c_]=0.f; } while(0)

// ---------------- conversion / small kernels ----------------
#define C0 524288
#define C1 (C0+65536)
#define C2 (C1+65536)
#define C3 (C2+65536)
#define C4 (C3+262144)
#define C5 (C4+262144)
__global__ __launch_bounds__(256) void k_convert_all(
    const float* __restrict__ x,  const float* __restrict__ Wq,
    const float* __restrict__ Wk, const float* __restrict__ Wv,
    const float* __restrict__ Wr, const float* __restrict__ Wo)
{
    int i = blockIdx.x * 256 + threadIdx.x;
    const float* s; __half* d; int off;
    if (i < C0)      { s = x;  d = g_xh;  off = i; }
    else if (i < C1) { s = Wq; d = g_wqh; off = i - C0; }
    else if (i < C2) { s = Wk; d = g_wkh; off = i - C1; }
    else if (i < C3) { s = Wv; d = g_wvh; off = i - C2; }
    else if (i < C4) { s = Wr; d = g_wrh; off = i - C3; }
    else             { s = Wo; d = g_woh; off = i - C4; }
    float4 v = ((const float4*)s)[off];
    *(__half2*)&d[off*4]   = __floats2half2_rn(v.x, v.y);
    *(__half2*)&d[off*4+2] = __floats2half2_rn(v.z, v.w);
}

__global__ __launch_bounds__(256) void k_beff(const float* __restrict__ br,
                                              const float* __restrict__ Wo,
                                              const float* __restrict__ bo) {
    __shared__ float sm[8][32];
    int tx = threadIdx.x & 31, ty = threadIdx.x >> 5;
    int n = blockIdx.x * 32 + tx;
    float p = 0.f;
    for (int k = ty; k < 4*DM; k += 8) p += br[k] * Wo[(long)k*DM + n];
    sm[ty][tx] = p;
    __syncthreads();
    if (ty == 0) {
        float s = bo[n];
        #pragma unroll
        for (int w = 0; w < 8; w++) s += sm[w][tx];
        g_beff[n] = s;
    }
}

// ---------------- QKV + Weff (merged) ----------------
__global__ __launch_bounds__(256,2) void k_qkv_weff(
    const float* __restrict__ bq, const float* __restrict__ bk, const float* __restrict__ bv) {
    extern __shared__ __half dsm[];
    float acc[4][4][4]; ACC_ZERO(acc);
    if (blockIdx.y < 32) {
        int z = blockIdx.z;
        const __half* W = (z == 0) ? g_wqh : (z == 1) ? g_wkh : g_wvh;
        const float* b = (z == 0) ? bq : (z == 1) ? bk : bv;
        __half* O = (z == 0) ? g_Q : (z == 1) ? g_K : g_V;
        gemm_acc<false>(acc, dsm, g_xh, W, blockIdx.y*BM, blockIdx.x*BN, DM/BK, DM, DM);
        epi<true,true>(acc, b, O, blockIdx.y*BM, blockIdx.x*BN, DM, 1.f);
    } else {
        int idx = (blockIdx.y - 32) * 12 + blockIdx.z * 4 + blockIdx.x;
        if (idx >= 64) return;
        int r = idx >> 4, t = idx & 15;
        gemm_acc<false>(acc, dsm, g_wrh + (long)r*DM*DM, g_woh + (long)r*DM*DM,
                        (t >> 2)*BM, (t & 3)*BN, DM/BK, DM, DM);
        epi<true,false>(acc, nullptr, g_weff + (long)r*DM*DM, (t >> 2)*BM, (t & 3)*BN, DM, 1.f);
    }
}

// ---------------- scores (triangle) + Ud, one launch ----------------
__global__ __launch_bounds__(256,2) void k_scores_u() {
    extern __shared__ __half dsm[];
    float acc[4][4][4]; ACC_ZERO(acc);
    int id = blockIdx.x;
    if (id < 272) {
        int b = id / 136, t = id % 136;
        int i = (int)((sqrtf(8.f*t + 1.f) - 1.f) * 0.5f);
        while ((i+1)*(i+2)/2 <= t) ++i;
        while (i*(i+1)/2 > t) --i;
        int j = t - i*(i+1)/2;
        gemm_acc<true>(acc, dsm, g_Q + (long)b*SQ*DM, g_K + (long)b*SQ*DM,
                       i*BM, j*BN, DM/BK, DM, DM);
        epi<false,false>(acc, nullptr, g_scores + (long)b*SQ*SQ, i*BM, j*BN, SQ,
                         0.044194173824159216f);
    } else {
        int u = id - 272;               // 0..239
        int b = u / 120, v = u % 120, y = v / 4, xc = v % 4;
        int r, i0, rowoff;
        if (y < 16)      { r = 0; i0 = y*128;      rowoff = 0;    }
        else if (y < 24) { r = 1; i0 = (y-16)*128; rowoff = 2048; }
        else if (y < 28) { r = 2; i0 = (y-24)*128; rowoff = 3072; }
        else             { r = 3; i0 = (y-28)*128; rowoff = 3584; }
        int rate = 1 << r;
        gemm_acc<false>(acc, dsm, g_V + (long)b*SQ*DM, g_weff + (long)r*DM*DM,
                        i0, xc*BN, DM/BK, rate*DM, DM);
        epi<true,false>(acc, nullptr, g_ud + (long)b*UDB + (long)rowoff*DM,
                        i0, xc*BN, DM, 1.f);
    }
}

// ---------------- out = sum_r attn_r @ Ud_r (2 split partials) ----------------
__global__ __launch_bounds__(256,2) void k_attnv_final() {
    extern __shared__ __half dsm[];
    float acc[4][4][4]; ACC_ZERO(acc);
    int b = blockIdx.z >> 1, split = blockIdx.z & 1;
    int i0 = blockIdx.y * BM, n0 = blockIdx.x * BN;
    if (split == 0) {
        int kmax = i0 + 128;                    // <= SQ
        gemm_acc<false>(acc, dsm, g_attn1 + (long)b*SQ*SQ, g_ud + (long)b*UDB,
                        i0, n0, kmax/BK, SQ, DM);
    } else {
        const __half* attns[3] = { g_attn2, g_attn4, g_attn8 };
        const int rowoffs[3] = { 2048, 3072, 3584 };
        #pragma unroll
        for (int s = 0; s < 3; s++) {
            int r = s + 1, rate = 1 << r, Sr = SQ >> r;
            int kmax = (i0 + 127)/rate + 1;
            if (kmax > Sr) kmax = Sr;
            int kt = (kmax + BK - 1) / BK;
            gemm_acc<false>(acc, dsm, attns[s] + (long)b*SQ*Sr,
                            g_ud + (long)b*UDB + (long)rowoffs[s]*DM,
                            i0, n0, kt, Sr, DM);
        }
    }
    float* pbuf = g_scores + (long)split*MS*DM + (long)b*SQ*DM;
    epi<false,false>(acc, nullptr, pbuf, i0, n0, DM, 1.f);
}

__global__ __launch_bounds__(256) void k_addout(float* __restrict__ out) {
    int i = blockIdx.x * 256 + threadIdx.x;
    const float4* p0 = (const float4*)g_scores;
    const float4* p1 = (const float4*)(g_scores + (long)MS*DM);
    float4 a = p0[i], b = p1[i];
    float4 bb = ((const float4*)g_beff)[i & 127];
    float4 o;
    o.x = a.x + b.x + bb.x; o.y = a.y + b.y + bb.y;
    o.z = a.z + b.z + bb.z; o.w = a.w + b.w + bb.w;
    ((float4*)out)[i] = o;
}

// ---------------- softmax: single exp pass, fused 4-rate sums, direct writes ----------------
__global__ __launch_bounds__(256) void softmax_kernel(float* __restrict__ avg_out)
{
    __shared__ float srow[SQ];
    __shared__ float evals[SQ];
    __shared__ float wred[8][4];
    __shared__ float wmax[8];

    int i = blockIdx.x;
    int b = blockIdx.y;
    int tid = threadIdx.x;
    int lane = tid & 31;
    int warp = tid >> 5;

    const float* sc = &g_scores[((long)b*SQ + i) * SQ];
    for (int j = tid; j <= i; j += 256) srow[j] = sc[j];
    __syncthreads();

    // global max over j<=i (shared across rates; softmax is shift-invariant)
    float mx = -1e30f;
    for (int j = tid; j <= i; j += 256) mx = fmaxf(mx, srow[j]);
    #pragma unroll
    for (int o = 16; o >= 1; o >>= 1) mx = fmaxf(mx, __shfl_xor_sync(0xffffffffu, mx, o));
    if (lane == 0) wmax[warp] = mx;
    __syncthreads();
    mx = wmax[0];
    #pragma unroll
    for (int w = 1; w < 8; w++) mx = fmaxf(mx, wmax[w]);

    // one exp pass: cache evals, accumulate all 4 nested sums
    float s1 = 0.f, s2 = 0.f, s4 = 0.f, s8 = 0.f;
    for (int j = tid; j <= i; j += 256) {
        float e = __expf(srow[j] - mx);
        evals[j] = e;
        s1 += e;
        if (!(j & 1)) { s2 += e;
            if (!(j & 3)) { s4 += e;
                if (!(j & 7)) s8 += e; } }
    }
    #pragma unroll
    for (int o = 16; o >= 1; o >>= 1) {
        s1 += __shfl_xor_sync(0xffffffffu, s1, o);
        s2 += __shfl_xor_sync(0xffffffffu, s2, o);
        s4 += __shfl_xor_sync(0xffffffffu, s4, o);
        s8 += __shfl_xor_sync(0xffffffffu, s8, o);
    }
    if (lane == 0) { wred[warp][0]=s1; wred[warp][1]=s2; wred[warp][2]=s4; wred[warp][3]=s8; }
    __syncthreads();   // also makes evals visible to all
    s1 = s2 = s4 = s8 = 0.f;
    #pragma unroll
    for (int w = 0; w < 8; w++) {
        s1 += wred[w][0]; s2 += wred[w][1]; s4 += wred[w][2]; s8 += wred[w][3];
    }
    float inv1 = 1.f/s1, inv2 = 1.f/s2, inv4 = 1.f/s4, inv8 = 1.f/s8;

    __half* a1 = g_attn1 + ((long)b*SQ + i) * SQ;
    __half* a2 = g_attn2 + ((long)b*SQ + i) * (SQ/2);
    __half* a4 = g_attn4 + ((long)b*SQ + i) * (SQ/4);
    __half* a8 = g_attn8 + ((long)b*SQ + i) * (SQ/8);
    float* out = avg_out + ((long)b*SQ + i) * SQ;

    // single stride-1 write pass: avg + all 4 compacted attn rows
    for (int j = tid; j <= i; j += 256) {
        float e = evals[j];
        float v1 = e * inv1;
        a1[j] = __float2half_rn(v1);
        float av = v1;
        if (!(j & 1)) {
            float v2 = e * inv2; a2[j >> 1] = __float2half_rn(v2); av += v2;
            if (!(j & 3)) {
                float v4 = e * inv4; a4[j >> 2] = __float2half_rn(v4); av += v4;
                if (!(j & 7)) {
                    float v8 = e * inv8; a8[j >> 3] = __float2half_rn(v8); av += v8;
                }
            }
        }
        out[j] = 0.25f * av;
    }
    for (int j = i + 1 + tid; j < SQ; j += 256) out[j] = 0.f;

    // zero tails up to what k_attnv_final's block-causal bound reads
    const int base = i | (BM - 1);
    #pragma unroll
    for (int rr = 0; rr < 4; rr++) {
        int rate = 1 << rr, Sr = SQ >> rr;
        int count = i/rate + 1;
        int mfill = ((base/rate + 1) + 63) & ~63;
        if (mfill > Sr) mfill = Sr;
        __half* ar = (rr==0) ? a1 : (rr==1) ? a2 : (rr==2) ? a4 : a8;
        for (int m = count + tid; m < mfill; m += 256) ar[m] = __float2half_rn(0.f);
    }
}

// ---------------- launch ----------------
extern "C" void kernel_launch(void* const* d_in, const int* in_sizes, int n_in,
                              void* d_out, int out_size) {
    const float* x  = (const float*)d_in[0];
    const float* Wq = (const float*)d_in[1];
    const float* bq = (const float*)d_in[2];
    const float* Wk = (const float*)d_in[3];
    const float* bk = (const float*)d_in[4];
    const float* Wv = (const float*)d_in[5];
    const float* bv = (const float*)d_in[6];
    const float* Wr = (const float*)d_in[7];
    const float* br = (const float*)d_in[8];
    const float* Wo = (const float*)d_in[9];
    const float* bo = (const float*)d_in[10];
    float* out = (float*)d_out;

    cudaFuncSetAttribute(k_qkv_weff,    cudaFuncAttributeMaxDynamicSharedMemorySize, DSMEM);
    cudaFuncSetAttribute(k_scores_u,    cudaFuncAttributeMaxDynamicSharedMemorySize, DSMEM);
    cudaFuncSetAttribute(k_attnv_final, cudaFuncAttributeMaxDynamicSharedMemorySize, DSMEM);

    dim3 blk(256);

    // fp32->fp16 conversions
    k_convert_all<<<C5/256, blk>>>(x, Wq, Wk, Wv, Wr, Wo);

    // beff = br_flat @ Wo + bo
    k_beff<<<dim3(16), blk>>>(br, Wo, bo);

    // QKV projections + Weff[r] = Wr[r] @ Wo_r
    k_qkv_weff<<<dim3(DM/BN, 38, 3), blk, DSMEM>>>(bq, bk, bv);

    // scores (272 triangle tiles) + Ud_r = V(dilated) @ Weff_r (240 tiles), one launch
    k_scores_u<<<dim3(512, 1, 1), blk, DSMEM>>>();

    // softmax for all rates + avg attention
    softmax_kernel<<<dim3(SQ, NB), blk>>>(out + (long)MS*DM);

    // out = sum_r attn_r @ Ud_r, split into 2 partials, then add beff
    k_attnv_final<<<dim3(DM/BN, SQ/BM, 4), blk, DSMEM>>>();
    k_addout<<<dim3(MS*DM/4/256), blk>>>(out);
}

// round 10
// speedup vs baseline: 8.9044x; 1.0622x over previous
#include <cuda_runtime.h>
#include <cuda_fp16.h>
#include <cstdint>
#include <math.h>

#define SQ 2048
#define DM 512
#define NB 2
#define MS (NB*SQ)   // 4096

#define BM 128
#define BN 128
#define BK 32
#define APITCH 40
#define BPITCH 136
#define ASTG (BM*APITCH)
#define BSTG 5120
#define NSTAGE 4
#define DSMEM (NSTAGE*(ASTG+BSTG)*2)   // 81920 bytes
#define UDB (3840*512)                 // per-batch Ud halves

// ---------------- scratch ----------------
__device__ __half g_xh[MS*DM];
__device__ __half g_wqh[DM*DM];
__device__ __half g_wkh[DM*DM];
__device__ __half g_wvh[DM*DM];
__device__ __half g_wrh[4*DM*DM];
__device__ __half g_woh[4*DM*DM];
__device__ __half g_weff[4*DM*DM];   // [2048 x 512]
__device__ float  g_beff[DM];
__device__ __half g_Q[MS*DM];
__device__ __half g_K[MS*DM];
__device__ __half g_V[MS*DM];
__device__ __half g_ud[NB*UDB];      // Ud_r rows r0:0 r1:2048 r2:3072 r3:3584
__device__ float  g_scores[(long)NB*SQ*SQ];   // scores; reused as partials 0-3
__device__ float  g_part2[4L*MS*DM];          // partials 4-7
__device__ __half g_attn1[(long)NB*SQ*SQ];
__device__ __half g_attn2[(long)NB*SQ*(SQ/2)];
__device__ __half g_attn4[(long)NB*SQ*(SQ/4)];
__device__ __half g_attn8[(long)NB*SQ*(SQ/8)];

// ---------------- PTX helpers ----------------
__device__ __forceinline__ void mma16(float* c, const uint32_t* a, const uint32_t* b) {
    asm volatile(
        "mma.sync.aligned.m16n8k16.row.col.f32.f16.f16.f32 "
        "{%0,%1,%2,%3}, {%4,%5,%6,%7}, {%8,%9}, {%0,%1,%2,%3};"
        : "+f"(c[0]), "+f"(c[1]), "+f"(c[2]), "+f"(c[3])
        : "r"(a[0]), "r"(a[1]), "r"(a[2]), "r"(a[3]), "r"(b[0]), "r"(b[1]));
}
__device__ __forceinline__ void ldsm4(uint32_t* r, uint32_t addr) {
    asm volatile("ldmatrix.sync.aligned.m8n8.x4.shared.b16 {%0,%1,%2,%3}, [%4];"
                 : "=r"(r[0]), "=r"(r[1]), "=r"(r[2]), "=r"(r[3]) : "r"(addr));
}
__device__ __forceinline__ void ldsm4t(uint32_t* r, uint32_t addr) {
    asm volatile("ldmatrix.sync.aligned.m8n8.x4.trans.shared.b16 {%0,%1,%2,%3}, [%4];"
                 : "=r"(r[0]), "=r"(r[1]), "=r"(r[2]), "=r"(r[3]) : "r"(addr));
}
__device__ __forceinline__ void cpa16(uint32_t saddr, const void* g) {
    asm volatile("cp.async.cg.shared.global [%0], [%1], 16;" :: "r"(saddr), "l"(g));
}
__device__ __forceinline__ void cp_commit() { asm volatile("cp.async.commit_group;"); }
__device__ __forceinline__ void cp_wait2()  { asm volatile("cp.async.wait_group 2;" ::: "memory"); }

// ---------------- accumulating 128x128 MMA core ----------------
template<bool NT>
__device__ void gemm_acc(float (&acc)[4][4][4], __half* dsm,
                         const __half* __restrict__ A, const __half* __restrict__ B,
                         int i0, int n0, int ktiles, int lda, int ldb)
{
    __half* As = dsm;
    __half* Bs = dsm + NSTAGE * ASTG;

    const int tid  = threadIdx.x;
    const int lane = tid & 31;
    const int wid  = tid >> 5;
    const int wm   = wid >> 2;
    const int wn   = wid & 3;
    const int quad = lane >> 3;
    const int wthr = lane & 7;

    const uint32_t a_base = (uint32_t)__cvta_generic_to_shared(As);
    const uint32_t b_base = (uint32_t)__cvta_generic_to_shared(Bs);

    auto issue = [&](int kt, int st) {
        const int k0 = kt * BK;
        const uint32_t ab = a_base + (uint32_t)st * ASTG * 2u;
        const uint32_t bb = b_base + (uint32_t)st * BSTG * 2u;
        #pragma unroll
        for (int j = 0; j < 2; j++) {
            int e = tid + j * 256;
            int m = e >> 2, kq = (e & 3) * 8;
            cpa16(ab + (uint32_t)(m * APITCH + kq) * 2u,
                  &A[(long)(i0 + m) * lda + k0 + kq]);
            if (NT) {
                cpa16(bb + (uint32_t)(m * APITCH + kq) * 2u,
                      &B[(long)(n0 + m) * ldb + k0 + kq]);
            } else {
                int kr = e >> 4, nq = (e & 15) * 8;
                cpa16(bb + (uint32_t)(kr * BPITCH + nq) * 2u,
                      &B[(long)(k0 + kr) * ldb + n0 + nq]);
            }
        }
    };

    __syncthreads();

    issue(0, 0);
    cp_commit();
    if (ktiles > 1) issue(1, 1);
    cp_commit();
    if (ktiles > 2) issue(2, 2);
    cp_commit();

    int cur = 0, wst = 3;
    for (int kt = 0; kt < ktiles; kt++) {
        cp_wait2();
        __syncthreads();

        if (kt + 3 < ktiles) issue(kt + 3, wst);
        cp_commit();

        const uint32_t ab = a_base + (uint32_t)cur * ASTG * 2u;
        const uint32_t bb = b_base + (uint32_t)cur * BSTG * 2u;

        #pragma unroll
        for (int ks = 0; ks < 2; ks++) {
            uint32_t af[4][4], bf[4][2];
            #pragma unroll
            for (int mt = 0; mt < 4; mt++) {
                int arow = wm*64 + mt*16 + wthr + (quad & 1) * 8;
                int acol = ks*16 + (quad >> 1) * 8;
                ldsm4(af[mt], ab + (uint32_t)(arow * APITCH + acol) * 2u);
            }
            #pragma unroll
            for (int nh = 0; nh < 2; nh++) {
                int nc = wn*32 + nh*16;
                uint32_t r[4];
                if (NT) {
                    int brow = nc + wthr + (quad >> 1) * 8;
                    int bcol = ks*16 + (quad & 1) * 8;
                    ldsm4(r, bb + (uint32_t)(brow * APITCH + bcol) * 2u);
                } else {
                    int brow = ks*16 + wthr + (quad & 1) * 8;
                    int bcol = nc + (quad >> 1) * 8;
                    ldsm4t(r, bb + (uint32_t)(brow * BPITCH + bcol) * 2u);
                }
                bf[nh*2+0][0] = r[0]; bf[nh*2+0][1] = r[1];
                bf[nh*2+1][0] = r[2]; bf[nh*2+1][1] = r[3];
            }
            #pragma unroll
            for (int mt = 0; mt < 4; mt++)
                #pragma unroll
                for (int nt = 0; nt < 4; nt++)
                    mma16(acc[mt][nt], af[mt], bf[nt]);
        }

        cur = (cur + 1 == NSTAGE) ? 0 : cur + 1;
        wst = (wst + 1 == NSTAGE) ? 0 : wst + 1;
    }
}

template<bool HOUT, bool BIAS>
__device__ __forceinline__ void epi(float (&acc)[4][4][4], const float* __restrict__ bias,
                                    void* __restrict__ Cv, int i0, int n0, int ldc, float alpha)
{
    const int tid  = threadIdx.x;
    const int lane = tid & 31;
    const int wid  = tid >> 5;
    const int wm   = wid >> 2;
    const int wn   = wid & 3;
    const int gq   = lane >> 2;
    const int tg   = lane & 3;
    #pragma unroll
    for (int nt = 0; nt < 4; nt++) {
        int col = n0 + wn*32 + nt*8 + tg*2;
        float bx = 0.f, by = 0.f;
        if (BIAS) { bx = bias[col]; by = bias[col+1]; }
        #pragma unroll
        for (int mt = 0; mt < 4; mt++) {
            int row = i0 + wm*64 + mt*16 + gq;
            const float* c = acc[mt][nt];
            float v0 = c[0]*alpha + bx, v1 = c[1]*alpha + by;
            float v2 = c[2]*alpha + bx, v3 = c[3]*alpha + by;
            if (HOUT) {
                __half* C = (__half*)Cv;
                *(__half2*)&C[(long)row*ldc + col]     = __floats2half2_rn(v0, v1);
                *(__half2*)&C[(long)(row+8)*ldc + col] = __floats2half2_rn(v2, v3);
            } else {
                float* C = (float*)Cv;
                *(float2*)&C[(long)row*ldc + col]     = make_float2(v0, v1);
                *(float2*)&C[(long)(row+8)*ldc + col] = make_float2(v2, v3);
            }
        }
    }
}

#define ACC_ZERO(acc) do { \
    _Pragma("unroll") for (int a_=0;a_<4;a_++) _Pragma("unroll") for (int b_=0;b_<4;b_++) \
    _Pragma("unroll") for (int c_=0;c_<4;c_++) acc[a_][b_][c_]=0.f; } while(0)

// ---------------- conversion / small kernels ----------------
#define C0 524288
#define C1 (C0+65536)
#define C2 (C1+65536)
#define C3 (C2+65536)
#define C4 (C3+262144)
#define C5 (C4+262144)
__global__ __launch_bounds__(256) void k_convert_all(
    const float* __restrict__ x,  const float* __restrict__ Wq,
    const float* __restrict__ Wk, const float* __restrict__ Wv,
    const float* __restrict__ Wr, const float* __restrict__ Wo)
{
    int i = blockIdx.x * 256 + threadIdx.x;
    const float* s; __half* d; int off;
    if (i < C0)      { s = x;  d = g_xh;  off = i; }
    else if (i < C1) { s = Wq; d = g_wqh; off = i - C0; }
    else if (i < C2) { s = Wk; d = g_wkh; off = i - C1; }
    else if (i < C3) { s = Wv; d = g_wvh; off = i - C2; }
    else if (i < C4) { s = Wr; d = g_wrh; off = i - C3; }
    else             { s = Wo; d = g_woh; off = i - C4; }
    float4 v = ((const float4*)s)[off];
    *(__half2*)&d[off*4]   = __floats2half2_rn(v.x, v.y);
    *(__half2*)&d[off*4+2] = __floats2half2_rn(v.z, v.w);
}

__global__ __launch_bounds__(256) void k_beff(const float* __restrict__ br,
                                              const float* __restrict__ Wo,
                                              const float* __restrict__ bo) {
    __shared__ float sm[8][32];
    int tx = threadIdx.x & 31, ty = threadIdx.x >> 5;
    int n = blockIdx.x * 32 + tx;
    float p = 0.f;
    for (int k = ty; k < 4*DM; k += 8) p += br[k] * Wo[(long)k*DM + n];
    sm[ty][tx] = p;
    __syncthreads();
    if (ty == 0) {
        float s = bo[n];
        #pragma unroll
        for (int w = 0; w < 8; w++) s += sm[w][tx];
        g_beff[n] = s;
    }
}

// ---------------- QKV + Weff (merged) ----------------
__global__ __launch_bounds__(256,2) void k_qkv_weff(
    const float* __restrict__ bq, const float* __restrict__ bk, const float* __restrict__ bv) {
    extern __shared__ __half dsm[];
    float acc[4][4][4]; ACC_ZERO(acc);
    if (blockIdx.y < 32) {
        int z = blockIdx.z;
        const __half* W = (z == 0) ? g_wqh : (z == 1) ? g_wkh : g_wvh;
        const float* b = (z == 0) ? bq : (z == 1) ? bk : bv;
        __half* O = (z == 0) ? g_Q : (z == 1) ? g_K : g_V;
        gemm_acc<false>(acc, dsm, g_xh, W, blockIdx.y*BM, blockIdx.x*BN, DM/BK, DM, DM);
        epi<true,true>(acc, b, O, blockIdx.y*BM, blockIdx.x*BN, DM, 1.f);
    } else {
        int idx = (blockIdx.y - 32) * 12 + blockIdx.z * 4 + blockIdx.x;
        if (idx >= 64) return;
        int r = idx >> 4, t = idx & 15;
        gemm_acc<false>(acc, dsm, g_wrh + (long)r*DM*DM, g_woh + (long)r*DM*DM,
                        (t >> 2)*BM, (t & 3)*BN, DM/BK, DM, DM);
        epi<true,false>(acc, nullptr, g_weff + (long)r*DM*DM, (t >> 2)*BM, (t & 3)*BN, DM, 1.f);
    }
}

// ---------------- scores (triangle) + Ud, one launch ----------------
__global__ __launch_bounds__(256,2) void k_scores_u() {
    extern __shared__ __half dsm[];
    float acc[4][4][4]; ACC_ZERO(acc);
    int id = blockIdx.x;
    if (id < 272) {
        int b = id / 136, t = id % 136;
        int i = (int)((sqrtf(8.f*t + 1.f) - 1.f) * 0.5f);
        while ((i+1)*(i+2)/2 <= t) ++i;
        while (i*(i+1)/2 > t) --i;
        int j = t - i*(i+1)/2;
        gemm_acc<true>(acc, dsm, g_Q + (long)b*SQ*DM, g_K + (long)b*SQ*DM,
                       i*BM, j*BN, DM/BK, DM, DM);
        epi<false,false>(acc, nullptr, g_scores + (long)b*SQ*SQ, i*BM, j*BN, SQ,
                         0.044194173824159216f);
    } else {
        int u = id - 272;               // 0..239
        int b = u / 120, v = u % 120, y = v / 4, xc = v % 4;
        int r, i0, rowoff;
        if (y < 16)      { r = 0; i0 = y*128;      rowoff = 0;    }
        else if (y < 24) { r = 1; i0 = (y-16)*128; rowoff = 2048; }
        else if (y < 28) { r = 2; i0 = (y-24)*128; rowoff = 3072; }
        else             { r = 3; i0 = (y-28)*128; rowoff = 3584; }
        int rate = 1 << r;
        gemm_acc<false>(acc, dsm, g_V + (long)b*SQ*DM, g_weff + (long)r*DM*DM,
                        i0, xc*BN, DM/BK, rate*DM, DM);
        epi<true,false>(acc, nullptr, g_ud + (long)b*UDB + (long)rowoff*DM,
                        i0, xc*BN, DM, 1.f);
    }
}

// ---------------- out = sum_r attn_r @ Ud_r — 1024 uniform work items, 8 partials ----------
// item: y descending (LPT), split 0-3 = rate0 k-quarters, 4-5 = rate1 k-halves,
//       6 = rate2, 7 = rate3. Each item: kt = y+1 (split7: ceil((y+1)/2)).
__global__ __launch_bounds__(256,2) void k_attnv_bal() {
    extern __shared__ __half dsm[];
    float acc[4][4][4]; ACC_ZERO(acc);

    int it = blockIdx.x;            // 0..1023
    int y = 15 - (it >> 6);
    int rem = it & 63;
    int split = rem >> 3;           // 0..7
    int xc = (rem >> 1) & 3;
    int b = rem & 1;

    int i0 = y*128, n0 = xc*BN;
    const __half* A; const __half* Bm;
    int kt, k0e, lda;

    if (split < 4) {                 // rate 0 quarters
        kt  = y + 1;
        k0e = 32*(y+1)*split;
        A   = g_attn1 + (long)b*SQ*SQ;         lda = SQ;
        Bm  = g_ud + (long)b*UDB;
    } else if (split < 6) {          // rate 1 halves
        kt  = y + 1;
        k0e = 32*(y+1)*(split - 4);
        A   = g_attn2 + (long)b*SQ*(SQ/2);     lda = SQ/2;
        Bm  = g_ud + (long)b*UDB + 2048L*DM;
    } else if (split == 6) {         // rate 2
        kt  = y + 1;
        k0e = 0;
        A   = g_attn4 + (long)b*SQ*(SQ/4);     lda = SQ/4;
        Bm  = g_ud + (long)b*UDB + 3072L*DM;
    } else {                         // rate 3
        kt  = (y + 2) >> 1;
        k0e = 0;
        A   = g_attn8 + (long)b*SQ*(SQ/8);     lda = SQ/8;
        Bm  = g_ud + (long)b*UDB + 3584L*DM;
    }

    gemm_acc<false>(acc, dsm, A + k0e, Bm + (long)k0e*DM, i0, n0, kt, lda, DM);

    float* pbuf = (split < 4)
        ? g_scores + (long)split*MS*DM + (long)b*SQ*DM
        : g_part2  + (long)(split-4)*MS*DM + (long)b*SQ*DM;
    epi<false,false>(acc, nullptr, pbuf, i0, n0, DM, 1.f);
}

__global__ __launch_bounds__(256) void k_addout(float* __restrict__ out) {
    int i = blockIdx.x * 256 + threadIdx.x;      // float4 index, 524288 total
    float4 bb = ((const float4*)g_beff)[i & 127];
    float4 o = bb;
    #pragma unroll
    for (int s = 0; s < 4; s++) {
        float4 a = ((const float4*)(g_scores + (long)s*MS*DM))[i];
        o.x += a.x; o.y += a.y; o.z += a.z; o.w += a.w;
    }
    #pragma unroll
    for (int s = 0; s < 4; s++) {
        float4 a = ((const float4*)(g_part2 + (long)s*MS*DM))[i];
        o.x += a.x; o.y += a.y; o.z += a.z; o.w += a.w;
    }
    ((float4*)out)[i] = o;
}

// ---------------- softmax: single exp pass, fused 4-rate sums ----------------
__global__ __launch_bounds__(256) void softmax_kernel(float* __restrict__ avg_out)
{
    __shared__ float srow[SQ];
    __shared__ float evals[SQ];
    __shared__ float wred[8][4];
    __shared__ float wmax[8];

    int i = blockIdx.x;
    int b = blockIdx.y;
    int tid = threadIdx.x;
    int lane = tid & 31;
    int warp = tid >> 5;

    const float* sc = &g_scores[((long)b*SQ + i) * SQ];
    for (int j = tid; j <= i; j += 256) srow[j] = sc[j];
    __syncthreads();

    float mx = -1e30f;
    for (int j = tid; j <= i; j += 256) mx = fmaxf(mx, srow[j]);
    #pragma unroll
    for (int o = 16; o >= 1; o >>= 1) mx = fmaxf(mx, __shfl_xor_sync(0xffffffffu, mx, o));
    if (lane == 0) wmax[warp] = mx;
    __syncthreads();
    mx = wmax[0];
    #pragma unroll
    for (int w = 1; w < 8; w++) mx = fmaxf(mx, wmax[w]);

    float s1 = 0.f, s2 = 0.f, s4 = 0.f, s8 = 0.f;
    for (int j = tid; j <= i; j += 256) {
        float e = __expf(srow[j] - mx);
        evals[j] = e;
        s1 += e;
        if (!(j & 1)) { s2 += e;
            if (!(j & 3)) { s4 += e;
                if (!(j & 7)) s8 += e; } }
    }
    #pragma unroll
    for (int o = 16; o >= 1; o >>= 1) {
        s1 += __shfl_xor_sync(0xffffffffu, s1, o);
        s2 += __shfl_xor_sync(0xffffffffu, s2, o);
        s4 += __shfl_xor_sync(0xffffffffu, s4, o);
        s8 += __shfl_xor_sync(0xffffffffu, s8, o);
    }
    if (lane == 0) { wred[warp][0]=s1; wred[warp][1]=s2; wred[warp][2]=s4; wred[warp][3]=s8; }
    __syncthreads();
    s1 = s2 = s4 = s8 = 0.f;
    #pragma unroll
    for (int w = 0; w < 8; w++) {
        s1 += wred[w][0]; s2 += wred[w][1]; s4 += wred[w][2]; s8 += wred[w][3];
    }
    float inv1 = 1.f/s1, inv2 = 1.f/s2, inv4 = 1.f/s4, inv8 = 1.f/s8;

    __half* a1 = g_attn1 + ((long)b*SQ + i) * SQ;
    __half* a2 = g_attn2 + ((long)b*SQ + i) * (SQ/2);
    __half* a4 = g_attn4 + ((long)b*SQ + i) * (SQ/4);
    __half* a8 = g_attn8 + ((long)b*SQ + i) * (SQ/8);
    float* out = avg_out + ((long)b*SQ + i) * SQ;

    for (int j = tid; j <= i; j += 256) {
        float e = evals[j];
        float v1 = e * inv1;
        a1[j] = __float2half_rn(v1);
        float av = v1;
        if (!(j & 1)) {
            float v2 = e * inv2; a2[j >> 1] = __float2half_rn(v2); av += v2;
            if (!(j & 3)) {
                float v4 = e * inv4; a4[j >> 2] = __float2half_rn(v4); av += v4;
                if (!(j & 7)) {
                    float v8 = e * inv8; a8[j >> 3] = __float2half_rn(v8); av += v8;
                }
            }
        }
        out[j] = 0.25f * av;
    }
    for (int j = i + 1 + tid; j < SQ; j += 256) out[j] = 0.f;

    const int base = i | (BM - 1);
    #pragma unroll
    for (int rr = 0; rr < 4; rr++) {
        int rate = 1 << rr, Sr = SQ >> rr;
        int count = i/rate + 1;
        int mfill = ((base/rate + 1) + 63) & ~63;
        if (mfill > Sr) mfill = Sr;
        __half* ar = (rr==0) ? a1 : (rr==1) ? a2 : (rr==2) ? a4 : a8;
        for (int m = count + tid; m < mfill; m += 256) ar[m] = __float2half_rn(0.f);
    }
}

// ---------------- launch ----------------
extern "C" void kernel_launch(void* const* d_in, const int* in_sizes, int n_in,
                              void* d_out, int out_size) {
    const float* x  = (const float*)d_in[0];
    const float* Wq = (const float*)d_in[1];
    const float* bq = (const float*)d_in[2];
    const float* Wk = (const float*)d_in[3];
    const float* bk = (const float*)d_in[4];
    const float* Wv = (const float*)d_in[5];
    const float* bv = (const float*)d_in[6];
    const float* Wr = (const float*)d_in[7];
    const float* br = (const float*)d_in[8];
    const float* Wo = (const float*)d_in[9];
    const float* bo = (const float*)d_in[10];
    float* out = (float*)d_out;

    cudaFuncSetAttribute(k_qkv_weff, cudaFuncAttributeMaxDynamicSharedMemorySize, DSMEM);
    cudaFuncSetAttribute(k_scores_u, cudaFuncAttributeMaxDynamicSharedMemorySize, DSMEM);
    cudaFuncSetAttribute(k_attnv_bal,cudaFuncAttributeMaxDynamicSharedMemorySize, DSMEM);

    dim3 blk(256);

    // fp32->fp16 conversions
    k_convert_all<<<C5/256, blk>>>(x, Wq, Wk, Wv, Wr, Wo);

    // beff = br_flat @ Wo + bo
    k_beff<<<dim3(16), blk>>>(br, Wo, bo);

    // QKV projections + Weff[r] = Wr[r] @ Wo_r
    k_qkv_weff<<<dim3(DM/BN, 38, 3), blk, DSMEM>>>(bq, bk, bv);

    // scores (272 triangle tiles) + Ud (240 tiles), one launch
    k_scores_u<<<dim3(512, 1, 1), blk, DSMEM>>>();

    // softmax for all rates + avg attention
    softmax_kernel<<<dim3(SQ, NB), blk>>>(out + (long)MS*DM);

    // out = sum_r attn_r @ Ud_r: 1024 balanced items into 8 partial buffers
    k_attnv_bal<<<dim3(1024, 1, 1), blk, DSMEM>>>();
    k_addout<<<dim3(MS*DM/4/256), blk>>>(out);
}

// round 11
// speedup vs baseline: 9.4304x; 1.0591x over previous
#include <cuda_runtime.h>
#include <cuda_fp16.h>
#include <cstdint>
#include <math.h>

#define SQ 2048
#define DM 512
#define NB 2
#define MS (NB*SQ)   // 4096

#define BM 128
#define BN 128
#define BK 64
#define APITCH 72     // halves; [row][k] layout (A, NT-B); 144B row stride, conflict-free
#define BPITCH 136    // halves; [k][n] layout (NN-B)
#define ASTG (BM*APITCH)          // 9216 halves per stage
#define BSTG 9216                 // max(64*136=8704, 128*72=9216)
#define NSTAGE 3
#define DSMEM (NSTAGE*(ASTG+BSTG)*2)   // 110592 bytes
#define UDB (3840*512)                 // per-batch Ud halves

// ---------------- scratch ----------------
__device__ __half g_xh[MS*DM];
__device__ __half g_wqh[DM*DM];
__device__ __half g_wkh[DM*DM];
__device__ __half g_wvh[DM*DM];
__device__ __half g_wrh[4*DM*DM];
__device__ __half g_woh[4*DM*DM];
__device__ __half g_weff[4*DM*DM];   // [2048 x 512]
__device__ float  g_beff[DM];
__device__ __half g_Q[MS*DM];
__device__ __half g_K[MS*DM];
__device__ __half g_V[MS*DM];
__device__ __half g_ud[NB*UDB];      // Ud_r rows r0:0 r1:2048 r2:3072 r3:3584
__device__ float  g_scores[(long)NB*SQ*SQ];   // scores; reused as 4 partials [4][4096x512]
__device__ __half g_attn1[(long)NB*SQ*SQ];
__device__ __half g_attn2[(long)NB*SQ*(SQ/2)];
__device__ __half g_attn4[(long)NB*SQ*(SQ/4)];
__device__ __half g_attn8[(long)NB*SQ*(SQ/8)];

// ---------------- PTX helpers ----------------
__device__ __forceinline__ void mma16(float* c, const uint32_t* a, const uint32_t* b) {
    asm volatile(
        "mma.sync.aligned.m16n8k16.row.col.f32.f16.f16.f32 "
        "{%0,%1,%2,%3}, {%4,%5,%6,%7}, {%8,%9}, {%0,%1,%2,%3};"
        : "+f"(c[0]), "+f"(c[1]), "+f"(c[2]), "+f"(c[3])
        : "r"(a[0]), "r"(a[1]), "r"(a[2]), "r"(a[3]), "r"(b[0]), "r"(b[1]));
}
__device__ __forceinline__ void ldsm4(uint32_t* r, uint32_t addr) {
    asm volatile("ldmatrix.sync.aligned.m8n8.x4.shared.b16 {%0,%1,%2,%3}, [%4];"
                 : "=r"(r[0]), "=r"(r[1]), "=r"(r[2]), "=r"(r[3]) : "r"(addr));
}
__device__ __forceinline__ void ldsm4t(uint32_t* r, uint32_t addr) {
    asm volatile("ldmatrix.sync.aligned.m8n8.x4.trans.shared.b16 {%0,%1,%2,%3}, [%4];"
                 : "=r"(r[0]), "=r"(r[1]), "=r"(r[2]), "=r"(r[3]) : "r"(addr));
}
__device__ __forceinline__ void cpa16(uint32_t saddr, const void* g) {
    asm volatile("cp.async.cg.shared.global [%0], [%1], 16;" :: "r"(saddr), "l"(g));
}
__device__ __forceinline__ void cp_commit() { asm volatile("cp.async.commit_group;"); }
__device__ __forceinline__ void cp_wait1()  { asm volatile("cp.async.wait_group 1;" ::: "memory"); }

// ---------------- accumulating 128x128 MMA core, BK=64, 3-stage ----------------
template<bool NT>
__device__ void gemm_acc(float (&acc)[4][4][4], __half* dsm,
                         const __half* __restrict__ A, const __half* __restrict__ B,
                         int i0, int n0, int ktiles, int lda, int ldb)
{
    __half* As = dsm;
    __half* Bs = dsm + NSTAGE * ASTG;

    const int tid  = threadIdx.x;
    const int lane = tid & 31;
    const int wid  = tid >> 5;
    const int wm   = wid >> 2;
    const int wn   = wid & 3;
    const int quad = lane >> 3;
    const int wthr = lane & 7;

    const uint32_t a_base = (uint32_t)__cvta_generic_to_shared(As);
    const uint32_t b_base = (uint32_t)__cvta_generic_to_shared(Bs);

    auto issue = [&](int kt, int st) {
        const int k0 = kt * BK;
        const uint32_t ab = a_base + (uint32_t)st * ASTG * 2u;
        const uint32_t bb = b_base + (uint32_t)st * BSTG * 2u;
        #pragma unroll
        for (int j = 0; j < 4; j++) {
            int e = tid + j * 256;          // 0..1023
            int m = e >> 3, kq = (e & 7) * 8;
            cpa16(ab + (uint32_t)(m * APITCH + kq) * 2u,
                  &A[(long)(i0 + m) * lda + k0 + kq]);
            if (NT) {
                cpa16(bb + (uint32_t)(m * APITCH + kq) * 2u,
                      &B[(long)(n0 + m) * ldb + k0 + kq]);
            } else {
                int kr = e >> 4, nq = (e & 15) * 8;
                cpa16(bb + (uint32_t)(kr * BPITCH + nq) * 2u,
                      &B[(long)(k0 + kr) * ldb + n0 + nq]);
            }
        }
    };

    __syncthreads();   // previous segment's consumers done before overwriting stage 0

    issue(0, 0);
    cp_commit();
    if (ktiles > 1) issue(1, 1);
    cp_commit();

    int cur = 0, wst = 2;
    for (int kt = 0; kt < ktiles; kt++) {
        cp_wait1();            // group for tile kt complete (<=1 newer pending)
        __syncthreads();       // all warps done with stage wst's previous contents

        if (kt + 2 < ktiles) issue(kt + 2, wst);
        cp_commit();           // one commit per iter, possibly empty

        const uint32_t ab = a_base + (uint32_t)cur * ASTG * 2u;
        const uint32_t bb = b_base + (uint32_t)cur * BSTG * 2u;

        #pragma unroll
        for (int ks = 0; ks < 4; ks++) {
            uint32_t af[4][4], bf[4][2];
            #pragma unroll
            for (int mt = 0; mt < 4; mt++) {
                int arow = wm*64 + mt*16 + wthr + (quad & 1) * 8;
                int acol = ks*16 + (quad >> 1) * 8;
                ldsm4(af[mt], ab + (uint32_t)(arow * APITCH + acol) * 2u);
            }
            #pragma unroll
            for (int nh = 0; nh < 2; nh++) {
                int nc = wn*32 + nh*16;
                uint32_t r[4];
                if (NT) {
                    int brow = nc + wthr + (quad >> 1) * 8;
                    int bcol = ks*16 + (quad & 1) * 8;
                    ldsm4(r, bb + (uint32_t)(brow * APITCH + bcol) * 2u);
                } else {
                    int brow = ks*16 + wthr + (quad & 1) * 8;
                    int bcol = nc + (quad >> 1) * 8;
                    ldsm4t(r, bb + (uint32_t)(brow * BPITCH + bcol) * 2u);
                }
                bf[nh*2+0][0] = r[0]; bf[nh*2+0][1] = r[1];
                bf[nh*2+1][0] = r[2]; bf[nh*2+1][1] = r[3];
            }
            #pragma unroll
            for (int mt = 0; mt < 4; mt++)
                #pragma unroll
                for (int nt = 0; nt < 4; nt++)
                    mma16(acc[mt][nt], af[mt], bf[nt]);
        }

        cur = (cur + 1 == NSTAGE) ? 0 : cur + 1;
        wst = (wst + 1 == NSTAGE) ? 0 : wst + 1;
    }
}

template<bool HOUT, bool BIAS>
__device__ __forceinline__ void epi(float (&acc)[4][4][4], const float* __restrict__ bias,
                                    void* __restrict__ Cv, int i0, int n0, int ldc, float alpha)
{
    const int tid  = threadIdx.x;
    const int lane = tid & 31;
    const int wid  = tid >> 5;
    const int wm   = wid >> 2;
    const int wn   = wid & 3;
    const int gq   = lane >> 2;
    const int tg   = lane & 3;
    #pragma unroll
    for (int nt = 0; nt < 4; nt++) {
        int col = n0 + wn*32 + nt*8 + tg*2;
        float bx = 0.f, by = 0.f;
        if (BIAS) { bx = bias[col]; by = bias[col+1]; }
        #pragma unroll
        for (int mt = 0; mt < 4; mt++) {
            int row = i0 + wm*64 + mt*16 + gq;
            const float* c = acc[mt][nt];
            float v0 = c[0]*alpha + bx, v1 = c[1]*alpha + by;
            float v2 = c[2]*alpha + bx, v3 = c[3]*alpha + by;
            if (HOUT) {
                __half* C = (__half*)Cv;
                *(__half2*)&C[(long)row*ldc + col]     = __floats2half2_rn(v0, v1);
                *(__half2*)&C[(long)(row+8)*ldc + col] = __floats2half2_rn(v2, v3);
            } else {
                float* C = (float*)Cv;
                *(float2*)&C[(long)row*ldc + col]     = make_float2(v0, v1);
                *(float2*)&C[(long)(row+8)*ldc + col] = make_float2(v2, v3);
            }
        }
    }
}

#define ACC_ZERO(acc) do { \
    _Pragma("unroll") for (int a_=0;a_<4;a_++) _Pragma("unroll") for (int b_=0;b_<4;b_++) \
    _Pragma("unroll") for (int c_=0;c_<4;c_++) acc[a_][b_][c_]=0.f; } while(0)

// ---------------- conversion / small kernels ----------------
#define C0 524288
#define C1 (C0+65536)
#define C2 (C1+65536)
#define C3 (C2+65536)
#define C4 (C3+262144)
#define C5 (C4+262144)
__global__ __launch_bounds__(256) void k_convert_all(
    const float* __restrict__ x,  const float* __restrict__ Wq,
    const float* __restrict__ Wk, const float* __restrict__ Wv,
    const float* __restrict__ Wr, const float* __restrict__ Wo)
{
    int i = blockIdx.x * 256 + threadIdx.x;
    const float* s; __half* d; int off;
    if (i < C0)      { s = x;  d = g_xh;  off = i; }
    else if (i < C1) { s = Wq; d = g_wqh; off = i - C0; }
    else if (i < C2) { s = Wk; d = g_wkh; off = i - C1; }
    else if (i < C3) { s = Wv; d = g_wvh; off = i - C2; }
    else if (i < C4) { s = Wr; d = g_wrh; off = i - C3; }
    else             { s = Wo; d = g_woh; off = i - C4; }
    float4 v = ((const float4*)s)[off];
    *(__half2*)&d[off*4]   = __floats2half2_rn(v.x, v.y);
    *(__half2*)&d[off*4+2] = __floats2half2_rn(v.z, v.w);
}

__global__ __launch_bounds__(256) void k_beff(const float* __restrict__ br,
                                              const float* __restrict__ Wo,
                                              const float* __restrict__ bo) {
    __shared__ float sm[8][32];
    int tx = threadIdx.x & 31, ty = threadIdx.x >> 5;
    int n = blockIdx.x * 32 + tx;
    float p = 0.f;
    for (int k = ty; k < 4*DM; k += 8) p += br[k] * Wo[(long)k*DM + n];
    sm[ty][tx] = p;
    __syncthreads();
    if (ty == 0) {
        float s = bo[n];
        #pragma unroll
        for (int w = 0; w < 8; w++) s += sm[w][tx];
        g_beff[n] = s;
    }
}

// ---------------- QKV + Weff (merged) ----------------
__global__ __launch_bounds__(256,2) void k_qkv_weff(
    const float* __restrict__ bq, const float* __restrict__ bk, const float* __restrict__ bv) {
    extern __shared__ __half dsm[];
    float acc[4][4][4]; ACC_ZERO(acc);
    if (blockIdx.y < 32) {
        int z = blockIdx.z;
        const __half* W = (z == 0) ? g_wqh : (z == 1) ? g_wkh : g_wvh;
        const float* b = (z == 0) ? bq : (z == 1) ? bk : bv;
        __half* O = (z == 0) ? g_Q : (z == 1) ? g_K : g_V;
        gemm_acc<false>(acc, dsm, g_xh, W, blockIdx.y*BM, blockIdx.x*BN, DM/BK, DM, DM);
        epi<true,true>(acc, b, O, blockIdx.y*BM, blockIdx.x*BN, DM, 1.f);
    } else {
        int idx = (blockIdx.y - 32) * 12 + blockIdx.z * 4 + blockIdx.x;
        if (idx >= 64) return;
        int r = idx >> 4, t = idx & 15;
        gemm_acc<false>(acc, dsm, g_wrh + (long)r*DM*DM, g_woh + (long)r*DM*DM,
                        (t >> 2)*BM, (t & 3)*BN, DM/BK, DM, DM);
        epi<true,false>(acc, nullptr, g_weff + (long)r*DM*DM, (t >> 2)*BM, (t & 3)*BN, DM, 1.f);
    }
}

// ---------------- scores (triangle) + Ud, one launch ----------------
__global__ __launch_bounds__(256,2) void k_scores_u() {
    extern __shared__ __half dsm[];
    float acc[4][4][4]; ACC_ZERO(acc);
    int id = blockIdx.x;
    if (id < 272) {
        int b = id / 136, t = id % 136;
        int i = (int)((sqrtf(8.f*t + 1.f) - 1.f) * 0.5f);
        while ((i+1)*(i+2)/2 <= t) ++i;
        while (i*(i+1)/2 > t) --i;
        int j = t - i*(i+1)/2;
        gemm_acc<true>(acc, dsm, g_Q + (long)b*SQ*DM, g_K + (long)b*SQ*DM,
                       i*BM, j*BN, DM/BK, DM, DM);
        epi<false,false>(acc, nullptr, g_scores + (long)b*SQ*SQ, i*BM, j*BN, SQ,
                         0.044194173824159216f);
    } else {
        int u = id - 272;               // 0..239
        int b = u / 120, v = u % 120, y = v / 4, xc = v % 4;
        int r, i0, rowoff;
        if (y < 16)      { r = 0; i0 = y*128;      rowoff = 0;    }
        else if (y < 24) { r = 1; i0 = (y-16)*128; rowoff = 2048; }
        else if (y < 28) { r = 2; i0 = (y-24)*128; rowoff = 3072; }
        else             { r = 3; i0 = (y-28)*128; rowoff = 3584; }
        int rate = 1 << r;
        gemm_acc<false>(acc, dsm, g_V + (long)b*SQ*DM, g_weff + (long)r*DM*DM,
                        i0, xc*BN, DM/BK, rate*DM, DM);
        epi<true,false>(acc, nullptr, g_ud + (long)b*UDB + (long)rowoff*DM,
                        i0, xc*BN, DM, 1.f);
    }
}

// ---------------- out = sum_r attn_r @ Ud_r — 512 items, 4 partial buffers ----------
// split 0/1 = rate0 k-halves, 2 = rate1 whole, 3 = rate2 + rate3 (two acc calls).
// y descending (LPT); kt64 per item <= 16 vs mean depth 13.8.
__global__ __launch_bounds__(256,2) void k_attnv_bal() {
    extern __shared__ __half dsm[];
    float acc[4][4][4]; ACC_ZERO(acc);

    int it = blockIdx.x;            // 0..511
    int y = 15 - (it >> 5);
    int rem = it & 31;
    int split = rem >> 3;           // 0..3
    int xc = (rem >> 1) & 3;
    int b = rem & 1;

    int i0 = y*128, n0 = xc*BN;

    if (split == 0) {
        gemm_acc<false>(acc, dsm, g_attn1 + (long)b*SQ*SQ, g_ud + (long)b*UDB,
                        i0, n0, y+1, SQ, DM);
    } else if (split == 1) {
        int k0e = 64*(y+1);
        gemm_acc<false>(acc, dsm, g_attn1 + (long)b*SQ*SQ + k0e,
                        g_ud + (long)b*UDB + (long)k0e*DM, i0, n0, y+1, SQ, DM);
    } else if (split == 2) {
        gemm_acc<false>(acc, dsm, g_attn2 + (long)b*SQ*(SQ/2),
                        g_ud + (long)b*UDB + 2048L*DM, i0, n0, y+1, SQ/2, DM);
    } else {
        int kt2 = (y + 2) >> 1;     // ceil((y+1)/2)
        int kt3 = (y + 4) >> 2;     // ceil((y+1)/4)
        gemm_acc<false>(acc, dsm, g_attn4 + (long)b*SQ*(SQ/4),
                        g_ud + (long)b*UDB + 3072L*DM, i0, n0, kt2, SQ/4, DM);
        gemm_acc<false>(acc, dsm, g_attn8 + (long)b*SQ*(SQ/8),
                        g_ud + (long)b*UDB + 3584L*DM, i0, n0, kt3, SQ/8, DM);
    }

    float* pbuf = g_scores + (long)split*MS*DM + (long)b*SQ*DM;
    epi<false,false>(acc, nullptr, pbuf, i0, n0, DM, 1.f);
}

__global__ __launch_bounds__(256) void k_addout(float* __restrict__ out) {
    int i = blockIdx.x * 256 + threadIdx.x;      // float4 index, 524288 total
    float4 bb = ((const float4*)g_beff)[i & 127];
    float4 o = bb;
    #pragma unroll
    for (int s = 0; s < 4; s++) {
        float4 a = ((const float4*)(g_scores + (long)s*MS*DM))[i];
        o.x += a.x; o.y += a.y; o.z += a.z; o.w += a.w;
    }
    ((float4*)out)[i] = o;
}

// ---------------- softmax: single exp pass, fused 4-rate sums ----------------
__global__ __launch_bounds__(256) void softmax_kernel(float* __restrict__ avg_out)
{
    __shared__ float srow[SQ];
    __shared__ float evals[SQ];
    __shared__ float wred[8][4];
    __shared__ float wmax[8];

    int i = blockIdx.x;
    int b = blockIdx.y;
    int tid = threadIdx.x;
    int lane = tid & 31;
    int warp = tid >> 5;

    const float* sc = &g_scores[((long)b*SQ + i) * SQ];
    for (int j = tid; j <= i; j += 256) srow[j] = sc[j];
    __syncthreads();

    float mx = -1e30f;
    for (int j = tid; j <= i; j += 256) mx = fmaxf(mx, srow[j]);
    #pragma unroll
    for (int o = 16; o >= 1; o >>= 1) mx = fmaxf(mx, __shfl_xor_sync(0xffffffffu, mx, o));
    if (lane == 0) wmax[warp] = mx;
    __syncthreads();
    mx = wmax[0];
    #pragma unroll
    for (int w = 1; w < 8; w++) mx = fmaxf(mx, wmax[w]);

    float s1 = 0.f, s2 = 0.f, s4 = 0.f, s8 = 0.f;
    for (int j = tid; j <= i; j += 256) {
        float e = __expf(srow[j] - mx);
        evals[j] = e;
        s1 += e;
        if (!(j & 1)) { s2 += e;
            if (!(j & 3)) { s4 += e;
                if (!(j & 7)) s8 += e; } }
    }
    #pragma unroll
    for (int o = 16; o >= 1; o >>= 1) {
        s1 += __shfl_xor_sync(0xffffffffu, s1, o);
        s2 += __shfl_xor_sync(0xffffffffu, s2, o);
        s4 += __shfl_xor_sync(0xffffffffu, s4, o);
        s8 += __shfl_xor_sync(0xffffffffu, s8, o);
    }
    if (lane == 0) { wred[warp][0]=s1; wred[warp][1]=s2; wred[warp][2]=s4; wred[warp][3]=s8; }
    __syncthreads();
    s1 = s2 = s4 = s8 = 0.f;
    #pragma unroll
    for (int w = 0; w < 8; w++) {
        s1 += wred[w][0]; s2 += wred[w][1]; s4 += wred[w][2]; s8 += wred[w][3];
    }
    float inv1 = 1.f/s1, inv2 = 1.f/s2, inv4 = 1.f/s4, inv8 = 1.f/s8;

    __half* a1 = g_attn1 + ((long)b*SQ + i) * SQ;
    __half* a2 = g_attn2 + ((long)b*SQ + i) * (SQ/2);
    __half* a4 = g_attn4 + ((long)b*SQ + i) * (SQ/4);
    __half* a8 = g_attn8 + ((long)b*SQ + i) * (SQ/8);
    float* out = avg_out + ((long)b*SQ + i) * SQ;

    for (int j = tid; j <= i; j += 256) {
        float e = evals[j];
        float v1 = e * inv1;
        a1[j] = __float2half_rn(v1);
        float av = v1;
        if (!(j & 1)) {
            float v2 = e * inv2; a2[j >> 1] = __float2half_rn(v2); av += v2;
            if (!(j & 3)) {
                float v4 = e * inv4; a4[j >> 2] = __float2half_rn(v4); av += v4;
                if (!(j & 7)) {
                    float v8 = e * inv8; a8[j >> 3] = __float2half_rn(v8); av += v8;
                }
            }
        }
        out[j] = 0.25f * av;
    }
    for (int j = i + 1 + tid; j < SQ; j += 256) out[j] = 0.f;

    const int base = i | (BM - 1);
    #pragma unroll
    for (int rr = 0; rr < 4; rr++) {
        int rate = 1 << rr, Sr = SQ >> rr;
        int count = i/rate + 1;
        int mfill = ((base/rate + 1) + 63) & ~63;
        if (mfill > Sr) mfill = Sr;
        __half* ar = (rr==0) ? a1 : (rr==1) ? a2 : (rr==2) ? a4 : a8;
        for (int m = count + tid; m < mfill; m += 256) ar[m] = __float2half_rn(0.f);
    }
}

// ---------------- launch ----------------
extern "C" void kernel_launch(void* const* d_in, const int* in_sizes, int n_in,
                              void* d_out, int out_size) {
    const float* x  = (const float*)d_in[0];
    const float* Wq = (const float*)d_in[1];
    const float* bq = (const float*)d_in[2];
    const float* Wk = (const float*)d_in[3];
    const float* bk = (const float*)d_in[4];
    const float* Wv = (const float*)d_in[5];
    const float* bv = (const float*)d_in[6];
    const float* Wr = (const float*)d_in[7];
    const float* br = (const float*)d_in[8];
    const float* Wo = (const float*)d_in[9];
    const float* bo = (const float*)d_in[10];
    float* out = (float*)d_out;

    cudaFuncSetAttribute(k_qkv_weff, cudaFuncAttributeMaxDynamicSharedMemorySize, DSMEM);
    cudaFuncSetAttribute(k_scores_u, cudaFuncAttributeMaxDynamicSharedMemorySize, DSMEM);
    cudaFuncSetAttribute(k_attnv_bal,cudaFuncAttributeMaxDynamicSharedMemorySize, DSMEM);

    dim3 blk(256);

    // fp32->fp16 conversions
    k_convert_all<<<C5/256, blk>>>(x, Wq, Wk, Wv, Wr, Wo);

    // beff = br_flat @ Wo + bo
    k_beff<<<dim3(16), blk>>>(br, Wo, bo);

    // QKV projections + Weff[r] = Wr[r] @ Wo_r
    k_qkv_weff<<<dim3(DM/BN, 38, 3), blk, DSMEM>>>(bq, bk, bv);

    // scores (272 triangle tiles) + Ud (240 tiles), one launch
    k_scores_u<<<dim3(512, 1, 1), blk, DSMEM>>>();

    // softmax for all rates + avg attention
    softmax_kernel<<<dim3(SQ, NB), blk>>>(out + (long)MS*DM);

    // out = sum_r attn_r @ Ud_r: 512 balanced items into 4 partial buffers
    k_attnv_bal<<<dim3(512, 1, 1), blk, DSMEM>>>();
    k_addout<<<dim3(MS*DM/4/256), blk>>>(out);
}